// round 2
// baseline (speedup 1.0000x reference)
#include <cuda_runtime.h>

#define NCAP 10240            // node capacity for P tables
#define GCAP 20032            // group capacity

// Scratch (device globals: no allocations allowed)
__device__ float g_P[3 * NCAP * 128];   // Pa | Pb | Pc, each [nodes][128]
__device__ float g_Gc[GCAP * 128];      // per-group ctx term (+ b1 folded)

// ---------------------------------------------------------------------------
// Kernel A: P[part][n][j] = sum_k x[n][k] * W1[j][part*128 + k]
// grid: (ceil(nodes/32), 3), block: 128 (thread = output channel j)
// ---------------------------------------------------------------------------
__global__ __launch_bounds__(128) void precompute_P(
    const float* __restrict__ x, const float* __restrict__ W1, int nodes) {
  const int part = blockIdx.y;
  const int n0 = blockIdx.x * 32;
  __shared__ float xs[32 * 128];

  for (int i = threadIdx.x; i < 32 * 32; i += 128) {   // float4 units
    int n = i >> 5, c4 = i & 31;
    float4 v = make_float4(0.f, 0.f, 0.f, 0.f);
    if (n0 + n < nodes) v = ((const float4*)(x + (size_t)(n0 + n) * 128))[c4];
    ((float4*)(xs + n * 128))[c4] = v;
  }
  __syncthreads();

  const int j = threadIdx.x;
  const float* wrow = W1 + (size_t)j * 384 + part * 128;
  float acc[32];
#pragma unroll
  for (int n = 0; n < 32; n++) acc[n] = 0.f;

  for (int k = 0; k < 128; k += 4) {
    const float4 w = *(const float4*)(wrow + k);
#pragma unroll
    for (int n = 0; n < 32; n++) {
      const float4 xv = *(const float4*)(xs + n * 128 + k);
      float a = acc[n];
      a = fmaf(w.x, xv.x, a);
      a = fmaf(w.y, xv.y, a);
      a = fmaf(w.z, xv.z, a);
      a = fmaf(w.w, xv.w, a);
      acc[n] = a;
    }
  }

  float* Pp = g_P + (size_t)part * NCAP * 128;
#pragma unroll
  for (int n = 0; n < 32; n++)
    if (n0 + n < nodes) Pp[(size_t)(n0 + n) * 128 + j] = acc[n];
}

// ---------------------------------------------------------------------------
// Kernel B: per-group context term.
// Gc[g][t] = (sum_{kk<20} Pc[idx[g*25][3+kk]][t]) / max(count(idx>0),1) + b1[t]
// grid: G, block: 128
// ---------------------------------------------------------------------------
__global__ __launch_bounds__(128) void group_ctx(
    const int* __restrict__ indices, const float* __restrict__ b1, int G) {
  const int g = blockIdx.x;
  if (g >= G) return;
  const int t = threadIdx.x;
  const int* ip = indices + (size_t)g * 25 * 23 + 3;
  const float* Pc = g_P + (size_t)2 * NCAP * 128;

  float s = 0.f;
  int cnt = 0;
#pragma unroll
  for (int kk = 0; kk < 20; kk++) {
    const int id = ip[kk];
    s += Pc[(size_t)id * 128 + t];
    cnt += (id > 0) ? 1 : 0;
  }
  const float norm = (float)(cnt > 0 ? cnt : 1);
  g_Gc[(size_t)g * 128 + t] = s / norm + b1[t];
}

// ---------------------------------------------------------------------------
// Kernel C: main fused MLP. Persistent blocks, one group (25 rows) per iter.
//  Phase A: h1[r][t] = relu(Pa[i0][t] + Pb[i1][t] + Gc[g][t])  (256 thr = 2 rows x 128 ch)
//  Phase B: h2[r][j]  = relu(b2[j] + sum_k W2[j][k] * h1[r][k]); out = h2 . W3 + b3
//           thread = (j = tid&63, rr = tid>>6); rows r = rr + 4m
// ---------------------------------------------------------------------------
__global__ __launch_bounds__(256) void mlp_main(
    const int* __restrict__ indices,
    const float* __restrict__ W2, const float* __restrict__ b2,
    const float* __restrict__ W3, const float* __restrict__ b3,
    float* __restrict__ out, int N, int G) {
  // Manual shared pool (h1s overreads up to index 3583 land inside w2t: harmless)
  __shared__ float pool[12088];
  float* h1s  = pool;             // 25*128 = 3200 floats
  float* w2t  = pool + 3200;      // [k][j] padded: 128*68 = 8704
  float* pbuf = pool + 11904;     // 8 warps * 7 partials = 56
  float* b2s  = pool + 11960;     // 64
  float* w3s  = pool + 12024;     // 64

  const int tid = threadIdx.x;

  // Stage W2 transposed ([k*68 + j]) + small vectors
  for (int i = tid; i < 64 * 128; i += 256) {
    const int j = i >> 7, k = i & 127;
    w2t[k * 68 + j] = W2[i];
  }
  if (tid < 64) { b2s[tid] = b2[tid]; w3s[tid] = W3[tid]; }
  const float b3v = b3[0];
  __syncthreads();

  const int t  = tid & 127, rh = tid >> 7;   // phase A mapping
  const int j  = tid & 63,  rr = tid >> 6;   // phase B mapping
  const int warp = tid >> 5;
  const float* Pa = g_P;
  const float* Pb = g_P + (size_t)NCAP * 128;

  for (int g = blockIdx.x; g < G; g += gridDim.x) {
    const int rowbase = g * 25;
    const int rows = min(25, N - rowbase);
    const float gcv = g_Gc[(size_t)g * 128 + t];

    // ---- Phase A ----
#pragma unroll
    for (int it = 0; it < 13; it++) {
      const int r = rh + 2 * it;
      if (r < rows) {
        const int* ip = indices + (size_t)(rowbase + r) * 23;
        const int i0 = ip[0], i1 = ip[1];
        const float v = Pa[(size_t)i0 * 128 + t] + Pb[(size_t)i1 * 128 + t] + gcv;
        h1s[r * 128 + t] = fmaxf(v, 0.f);
      }
    }
    __syncthreads();

    // ---- Phase B ----
    float acc[7];
#pragma unroll
    for (int m = 0; m < 7; m++) acc[m] = b2s[j];

#pragma unroll 8
    for (int k = 0; k < 128; k += 4) {
      const float w0 = w2t[(k + 0) * 68 + j];
      const float w1 = w2t[(k + 1) * 68 + j];
      const float w2v = w2t[(k + 2) * 68 + j];
      const float w3v = w2t[(k + 3) * 68 + j];
#pragma unroll
      for (int m = 0; m < 7; m++) {
        const float4 h = *(const float4*)(h1s + (rr + 4 * m) * 128 + k);
        float a = acc[m];
        a = fmaf(w0, h.x, a);
        a = fmaf(w1, h.y, a);
        a = fmaf(w2v, h.z, a);
        a = fmaf(w3v, h.w, a);
        acc[m] = a;
      }
    }

    const float w3j = w3s[j];
#pragma unroll
    for (int m = 0; m < 7; m++) {
      float p = fmaxf(acc[m], 0.f) * w3j;
#pragma unroll
      for (int off = 16; off > 0; off >>= 1)
        p += __shfl_xor_sync(0xffffffffu, p, off);
      if ((tid & 31) == 0) pbuf[warp * 7 + m] = p;
    }
    __syncthreads();

    if (tid < rows) {
      const int r = tid;
      const int mm = r >> 2, rrr = r & 3;
      out[rowbase + r] = pbuf[(rrr * 2) * 7 + mm] + pbuf[(rrr * 2 + 1) * 7 + mm] + b3v;
    }
    __syncthreads();   // protect h1s/pbuf reuse next iteration
  }
}

// ---------------------------------------------------------------------------
extern "C" void kernel_launch(void* const* d_in, const int* in_sizes, int n_in,
                              void* d_out, int out_size) {
  const int*   indices = (const int*)d_in[0];
  // d_in[1] = nr (fixed 24 by problem definition)
  const float* x  = (const float*)d_in[2];
  const float* W1 = (const float*)d_in[3];
  const float* b1 = (const float*)d_in[4];
  const float* W2 = (const float*)d_in[5];
  const float* b2 = (const float*)d_in[6];
  const float* W3 = (const float*)d_in[7];
  const float* b3 = (const float*)d_in[8];
  float* out = (float*)d_out;

  const int N = in_sizes[0] / 23;          // 500000
  const int nodes = in_sizes[2] / 128;     // 10000
  const int G = (N - 2) / 25 + 1;          // 20000 groups

  dim3 gridA((nodes + 31) / 32, 3);
  precompute_P<<<gridA, 128>>>(x, W1, nodes);
  group_ctx<<<G, 128>>>(indices, b1, G);
  mlp_main<<<592, 256>>>(indices, W2, b2, W3, b3, out, N, G);
}

// round 3
// speedup vs baseline: 1.0042x; 1.0042x over previous
#include <cuda_runtime.h>

#define NCAP 10240            // node capacity for P tables
#define GCAP 20032            // group capacity

// Scratch (device globals: no allocations allowed)
__device__ float g_P[3 * NCAP * 128];   // Pa | Pb | Pc, each [nodes][128]
__device__ float g_Gc[GCAP * 128];      // per-group ctx term (+ b1 folded)

// ---------------------------------------------------------------------------
// Kernel A: P[part][n][j] = sum_k x[n][k] * W1[j][part*128 + k]
// grid: (ceil(nodes/32), 3), block: 128 (thread = output channel j)
// ---------------------------------------------------------------------------
__global__ __launch_bounds__(128) void precompute_P(
    const float* __restrict__ x, const float* __restrict__ W1, int nodes) {
  const int part = blockIdx.y;
  const int n0 = blockIdx.x * 32;
  __shared__ float xs[32 * 128];

  for (int i = threadIdx.x; i < 32 * 32; i += 128) {   // float4 units
    int n = i >> 5, c4 = i & 31;
    float4 v = make_float4(0.f, 0.f, 0.f, 0.f);
    if (n0 + n < nodes) v = ((const float4*)(x + (size_t)(n0 + n) * 128))[c4];
    ((float4*)(xs + n * 128))[c4] = v;
  }
  __syncthreads();

  const int j = threadIdx.x;
  const float* wrow = W1 + (size_t)j * 384 + part * 128;
  float acc[32];
#pragma unroll
  for (int n = 0; n < 32; n++) acc[n] = 0.f;

  for (int k = 0; k < 128; k += 4) {
    const float4 w = *(const float4*)(wrow + k);
#pragma unroll
    for (int n = 0; n < 32; n++) {
      const float4 xv = *(const float4*)(xs + n * 128 + k);
      float a = acc[n];
      a = fmaf(w.x, xv.x, a);
      a = fmaf(w.y, xv.y, a);
      a = fmaf(w.z, xv.z, a);
      a = fmaf(w.w, xv.w, a);
      acc[n] = a;
    }
  }

  float* Pp = g_P + (size_t)part * NCAP * 128;
#pragma unroll
  for (int n = 0; n < 32; n++)
    if (n0 + n < nodes) Pp[(size_t)(n0 + n) * 128 + j] = acc[n];
}

// ---------------------------------------------------------------------------
// Kernel B: per-group context term.
// Gc[g][t] = (sum_{kk<20} Pc[idx[g*25][3+kk]][t]) / max(count(idx>0),1) + b1[t]
// grid: G, block: 128
// ---------------------------------------------------------------------------
__global__ __launch_bounds__(128) void group_ctx(
    const int* __restrict__ indices, const float* __restrict__ b1, int G) {
  const int g = blockIdx.x;
  if (g >= G) return;
  const int t = threadIdx.x;
  const int* ip = indices + (size_t)g * 25 * 23 + 3;
  const float* Pc = g_P + (size_t)2 * NCAP * 128;

  float s = 0.f;
  int cnt = 0;
#pragma unroll
  for (int kk = 0; kk < 20; kk++) {
    const int id = ip[kk];
    s += Pc[(size_t)id * 128 + t];
    cnt += (id > 0) ? 1 : 0;
  }
  const float norm = (float)(cnt > 0 ? cnt : 1);
  g_Gc[(size_t)g * 128 + t] = s / norm + b1[t];
}

// ---------------------------------------------------------------------------
// Kernel C: main fused MLP. Persistent blocks, one group (25 rows) per iter.
//  Phase A: h1[r][t] = relu(Pa[i0][t] + Pb[i1][t] + Gc[g][t])  (256 thr = 2 rows x 128 ch)
//  Phase B: h2[r][j]  = relu(b2[j] + sum_k W2[j][k] * h1[r][k]); out = h2 . W3 + b3
//           thread = (j = tid&63, rr = tid>>6); rows r = rr + 4m
// ---------------------------------------------------------------------------
__global__ __launch_bounds__(256) void mlp_main(
    const int* __restrict__ indices,
    const float* __restrict__ W2, const float* __restrict__ b2,
    const float* __restrict__ W3, const float* __restrict__ b3,
    float* __restrict__ out, int N, int G) {
  // Manual shared pool (h1s overreads up to index 3583 land inside w2t: harmless)
  __shared__ float pool[12088];
  float* h1s  = pool;             // 25*128 = 3200 floats
  float* w2t  = pool + 3200;      // [k][j] padded: 128*68 = 8704
  float* pbuf = pool + 11904;     // 8 warps * 7 partials = 56
  float* b2s  = pool + 11960;     // 64
  float* w3s  = pool + 12024;     // 64

  const int tid = threadIdx.x;

  // Stage W2 transposed ([k*68 + j]) + small vectors
  for (int i = tid; i < 64 * 128; i += 256) {
    const int j = i >> 7, k = i & 127;
    w2t[k * 68 + j] = W2[i];
  }
  if (tid < 64) { b2s[tid] = b2[tid]; w3s[tid] = W3[tid]; }
  const float b3v = b3[0];
  __syncthreads();

  const int t  = tid & 127, rh = tid >> 7;   // phase A mapping
  const int j  = tid & 63,  rr = tid >> 6;   // phase B mapping
  const int warp = tid >> 5;
  const float* Pa = g_P;
  const float* Pb = g_P + (size_t)NCAP * 128;

  for (int g = blockIdx.x; g < G; g += gridDim.x) {
    const int rowbase = g * 25;
    const int rows = min(25, N - rowbase);
    const float gcv = g_Gc[(size_t)g * 128 + t];

    // ---- Phase A ----
#pragma unroll
    for (int it = 0; it < 13; it++) {
      const int r = rh + 2 * it;
      if (r < rows) {
        const int* ip = indices + (size_t)(rowbase + r) * 23;
        const int i0 = ip[0], i1 = ip[1];
        const float v = Pa[(size_t)i0 * 128 + t] + Pb[(size_t)i1 * 128 + t] + gcv;
        h1s[r * 128 + t] = fmaxf(v, 0.f);
      }
    }
    __syncthreads();

    // ---- Phase B ----
    float acc[7];
#pragma unroll
    for (int m = 0; m < 7; m++) acc[m] = b2s[j];

#pragma unroll 8
    for (int k = 0; k < 128; k += 4) {
      const float w0 = w2t[(k + 0) * 68 + j];
      const float w1 = w2t[(k + 1) * 68 + j];
      const float w2v = w2t[(k + 2) * 68 + j];
      const float w3v = w2t[(k + 3) * 68 + j];
#pragma unroll
      for (int m = 0; m < 7; m++) {
        const float4 h = *(const float4*)(h1s + (rr + 4 * m) * 128 + k);
        float a = acc[m];
        a = fmaf(w0, h.x, a);
        a = fmaf(w1, h.y, a);
        a = fmaf(w2v, h.z, a);
        a = fmaf(w3v, h.w, a);
        acc[m] = a;
      }
    }

    const float w3j = w3s[j];
#pragma unroll
    for (int m = 0; m < 7; m++) {
      float p = fmaxf(acc[m], 0.f) * w3j;
#pragma unroll
      for (int off = 16; off > 0; off >>= 1)
        p += __shfl_xor_sync(0xffffffffu, p, off);
      if ((tid & 31) == 0) pbuf[warp * 7 + m] = p;
    }
    __syncthreads();

    if (tid < rows) {
      const int r = tid;
      const int mm = r >> 2, rrr = r & 3;
      out[rowbase + r] = pbuf[(rrr * 2) * 7 + mm] + pbuf[(rrr * 2 + 1) * 7 + mm] + b3v;
    }
    __syncthreads();   // protect h1s/pbuf reuse next iteration
  }
}

// ---------------------------------------------------------------------------
extern "C" void kernel_launch(void* const* d_in, const int* in_sizes, int n_in,
                              void* d_out, int out_size) {
  const int*   indices = (const int*)d_in[0];
  // d_in[1] = nr (fixed 24 by problem definition)
  const float* x  = (const float*)d_in[2];
  const float* W1 = (const float*)d_in[3];
  const float* b1 = (const float*)d_in[4];
  const float* W2 = (const float*)d_in[5];
  const float* b2 = (const float*)d_in[6];
  const float* W3 = (const float*)d_in[7];
  const float* b3 = (const float*)d_in[8];
  float* out = (float*)d_out;

  const int N = in_sizes[0] / 23;          // 500000
  const int nodes = in_sizes[2] / 128;     // 10000
  const int G = (N - 2) / 25 + 1;          // 20000 groups

  dim3 gridA((nodes + 31) / 32, 3);
  precompute_P<<<gridA, 128>>>(x, W1, nodes);
  group_ctx<<<G, 128>>>(indices, b1, G);
  mlp_main<<<592, 256>>>(indices, W2, b2, W3, b3, out, N, G);
}

// round 6
// speedup vs baseline: 1.7300x; 1.7229x over previous
#include <cuda_runtime.h>
#include <cuda_bf16.h>
#include <cstdint>

#define NCAP 10240            // node capacity for P tables
#define GCAP 20032            // group capacity

// Scratch (device globals: no allocations allowed)
__device__ float g_P[3 * NCAP * 128];   // Pa | Pb | Pc, each [nodes][128]
__device__ float g_Gc[GCAP * 128];      // per-group ctx term (+ b1 folded)

// ---------------------------------------------------------------------------
// helpers
// ---------------------------------------------------------------------------
__device__ __forceinline__ uint32_t smem_u32(const void* p) {
  uint32_t a;
  asm("{ .reg .u64 t; cvta.to.shared.u64 t, %1; cvt.u32.u64 %0, t; }"
      : "=r"(a) : "l"(p));
  return a;
}

__device__ __forceinline__ uint32_t bpack(__nv_bfloat16 a, __nv_bfloat16 b) {
  __nv_bfloat162 t(a, b);          // .x = a (low half)
  return *reinterpret_cast<uint32_t*>(&t);
}

#define LDSM4(r0, r1, r2, r3, addr)                                          \
  asm volatile(                                                              \
      "ldmatrix.sync.aligned.m8n8.x4.shared.b16 {%0,%1,%2,%3}, [%4];"        \
      : "=r"(r0), "=r"(r1), "=r"(r2), "=r"(r3) : "r"(addr))

#define MMA16816(d, a0, a1, a2, a3, b0, b1)                                  \
  asm volatile(                                                              \
      "mma.sync.aligned.m16n8k16.row.col.f32.bf16.bf16.f32 "                 \
      "{%0,%1,%2,%3}, {%4,%5,%6,%7}, {%8,%9}, {%0,%1,%2,%3};"                \
      : "+f"((d)[0]), "+f"((d)[1]), "+f"((d)[2]), "+f"((d)[3])               \
      : "r"(a0), "r"(a1), "r"(a2), "r"(a3), "r"(b0), "r"(b1))

// ---------------------------------------------------------------------------
// Kernel A: P[part][n][j] = sum_k x[n][k] * W1[j][part*128 + k]
// ---------------------------------------------------------------------------
__global__ __launch_bounds__(128) void precompute_P(
    const float* __restrict__ x, const float* __restrict__ W1, int nodes) {
  const int part = blockIdx.y;
  const int n0 = blockIdx.x * 32;
  __shared__ float xs[32 * 128];

  for (int i = threadIdx.x; i < 32 * 32; i += 128) {
    int n = i >> 5, c4 = i & 31;
    float4 v = make_float4(0.f, 0.f, 0.f, 0.f);
    if (n0 + n < nodes) v = ((const float4*)(x + (size_t)(n0 + n) * 128))[c4];
    ((float4*)(xs + n * 128))[c4] = v;
  }
  __syncthreads();

  const int j = threadIdx.x;
  const float* wrow = W1 + (size_t)j * 384 + part * 128;
  float acc[32];
#pragma unroll
  for (int n = 0; n < 32; n++) acc[n] = 0.f;

  for (int k = 0; k < 128; k += 4) {
    const float4 w = *(const float4*)(wrow + k);
#pragma unroll
    for (int n = 0; n < 32; n++) {
      const float4 xv = *(const float4*)(xs + n * 128 + k);
      float a = acc[n];
      a = fmaf(w.x, xv.x, a);
      a = fmaf(w.y, xv.y, a);
      a = fmaf(w.z, xv.z, a);
      a = fmaf(w.w, xv.w, a);
      acc[n] = a;
    }
  }

  float* Pp = g_P + (size_t)part * NCAP * 128;
#pragma unroll
  for (int n = 0; n < 32; n++)
    if (n0 + n < nodes) Pp[(size_t)(n0 + n) * 128 + j] = acc[n];
}

// ---------------------------------------------------------------------------
// Kernel B: per-group context term (+ b1 folded in)
// ---------------------------------------------------------------------------
__global__ __launch_bounds__(128) void group_ctx(
    const int* __restrict__ indices, const float* __restrict__ b1, int G) {
  const int g = blockIdx.x;
  if (g >= G) return;
  const int t = threadIdx.x;
  const int* ip = indices + (size_t)g * 25 * 23 + 3;
  const float* Pc = g_P + (size_t)2 * NCAP * 128;

  float s = 0.f;
  int cnt = 0;
#pragma unroll
  for (int kk = 0; kk < 20; kk++) {
    const int id = ip[kk];
    s += Pc[(size_t)id * 128 + t];
    cnt += (id > 0) ? 1 : 0;
  }
  const float norm = (float)(cnt > 0 ? cnt : 1);
  g_Gc[(size_t)g * 128 + t] = s / norm + b1[t];
}

// ---------------------------------------------------------------------------
// Kernel C: warp-independent HMMA MLP. Each warp owns a 16-row tile.
//  Phase A: h1 = relu(Pa[i0]+Pb[i1]+Gc[g]) -> bf16 hi/lo into padded smem rows
//           Row layout: k 0..63 at bytes [0,128), k 64..127 at bytes [144,272)
//  Phase B: 3-pass mma.sync m16n8k16 bf16 (Ahi*Bhi + Ahi*Blo + Alo*Bhi)
//  Epi:     out = relu(D + b2) . W3 + b3   (register-resident, shfl reduce)
// ---------------------------------------------------------------------------
#define AROW 272                       // bytes per h1 row (16-aligned halves)
#define HALF_OFF 144                   // byte offset of channels 64..127
#define AHI_OFF 0
#define ALO_OFF (8 * 16 * AROW)        // 34816
#define BF_OFF (2 * (8 * 16 * AROW))   // 69632
#define BFRAG_N 2048                   // (8 ks * 8 n * 32 lanes) uint2 per pass
#define MISC_OFF (BF_OFF + 2 * BFRAG_N * 8)  // 102400
#define SMEM_BYTES (MISC_OFF + 768)

__global__ void __launch_bounds__(256, 2) mlp_main_mma(
    const int* __restrict__ indices,
    const float* __restrict__ W2, const float* __restrict__ b2,
    const float* __restrict__ W3, const float* __restrict__ b3,
    float* __restrict__ out, int N) {
  extern __shared__ char smem[];
  const uint32_t sbase = smem_u32(smem);

  const int tid = threadIdx.x;
  const int wid = tid >> 5;
  const int lane = tid & 31;

  uint2* Bhi = (uint2*)(smem + BF_OFF);
  uint2* Blo = Bhi + BFRAG_N;
  float* b2s = (float*)(smem + MISC_OFF);
  float* w3s = b2s + 64;

  // ---- Build W2 bf16 hi/lo B-fragments (layout: [ks][n][lane] uint2) ----
  for (int i = tid; i < BFRAG_N; i += 256) {
    const int ln = i & 31;
    const int n = (i >> 5) & 7;
    const int ks = i >> 8;
    const int ng = n * 8 + (ln >> 2);          // output channel 0..63
    const int k0 = ks * 16 + (ln & 3) * 2;     // k of b0 pair
    const float* wr = W2 + (size_t)ng * 128 + k0;
    const float w00 = wr[0], w01 = wr[1], w10 = wr[8], w11 = wr[9];
    __nv_bfloat16 h00 = __float2bfloat16(w00);
    __nv_bfloat16 h01 = __float2bfloat16(w01);
    __nv_bfloat16 h10 = __float2bfloat16(w10);
    __nv_bfloat16 h11 = __float2bfloat16(w11);
    __nv_bfloat16 l00 = __float2bfloat16(w00 - __bfloat162float(h00));
    __nv_bfloat16 l01 = __float2bfloat16(w01 - __bfloat162float(h01));
    __nv_bfloat16 l10 = __float2bfloat16(w10 - __bfloat162float(h10));
    __nv_bfloat16 l11 = __float2bfloat16(w11 - __bfloat162float(h11));
    Bhi[i] = make_uint2(bpack(h00, h01), bpack(h10, h11));
    Blo[i] = make_uint2(bpack(l00, l01), bpack(l10, l11));
  }
  if (tid < 64) { b2s[tid] = b2[tid]; w3s[tid] = W3[tid]; }
  const float b3v = b3[0];
  __syncthreads();

  const float* Pa = g_P;
  const float* Pb = g_P + (size_t)NCAP * 128;

  // Phase-A mapping: lane -> (row rl = lane>>1, half = lane&1)
  const int rl = lane >> 1;
  const int half = lane & 1;
  const int chbase = half * 64;
  char* ahi_st = smem + AHI_OFF + (size_t)(wid * 16 + rl) * AROW + half * HALF_OFF;
  char* alo_st = smem + ALO_OFF + (size_t)(wid * 16 + rl) * AROW + half * HALF_OFF;

  // ldmatrix addressing: lane -> (row, col-block)
  const uint32_t lrow = (lane < 16) ? lane : (lane - 16);
  const uint32_t lcol = (lane < 16) ? 0u : 16u;   // +8 cols in bytes
  const uint32_t ahi_ld = sbase + AHI_OFF + (wid * 16 + lrow) * AROW + lcol;
  const uint32_t alo_ld = sbase + ALO_OFF + (wid * 16 + lrow) * AROW + lcol;

  const int NTW = (N + 15) >> 4;
  const int wstride = gridDim.x * 8;

  for (int wt = blockIdx.x * 8 + wid; wt < NTW; wt += wstride) {
    const int rbase = wt << 4;
    const int grow = rbase + rl;

    // ---- Phase A: gather + relu + bf16 hi/lo split ----
    if (grow < N) {
      const int i0 = indices[(size_t)grow * 23 + 0];
      const int i1 = indices[(size_t)grow * 23 + 1];
      const int g = grow / 25;
      const float* pa = Pa + (size_t)i0 * 128 + chbase;
      const float* pb = Pb + (size_t)i1 * 128 + chbase;
      const float* gc = g_Gc + (size_t)g * 128 + chbase;
#pragma unroll
      for (int cc = 0; cc < 8; cc++) {
        const float4 a0 = *(const float4*)(pa + cc * 8);
        const float4 a1 = *(const float4*)(pa + cc * 8 + 4);
        const float4 p0 = *(const float4*)(pb + cc * 8);
        const float4 p1 = *(const float4*)(pb + cc * 8 + 4);
        const float4 g0 = *(const float4*)(gc + cc * 8);
        const float4 g1 = *(const float4*)(gc + cc * 8 + 4);
        float v[8];
        v[0] = fmaxf(a0.x + p0.x + g0.x, 0.f);
        v[1] = fmaxf(a0.y + p0.y + g0.y, 0.f);
        v[2] = fmaxf(a0.z + p0.z + g0.z, 0.f);
        v[3] = fmaxf(a0.w + p0.w + g0.w, 0.f);
        v[4] = fmaxf(a1.x + p1.x + g1.x, 0.f);
        v[5] = fmaxf(a1.y + p1.y + g1.y, 0.f);
        v[6] = fmaxf(a1.z + p1.z + g1.z, 0.f);
        v[7] = fmaxf(a1.w + p1.w + g1.w, 0.f);
        __nv_bfloat16 hi[8], lo[8];
#pragma unroll
        for (int q = 0; q < 8; q++) {
          hi[q] = __float2bfloat16(v[q]);
          lo[q] = __float2bfloat16(v[q] - __bfloat162float(hi[q]));
        }
        *(uint4*)(ahi_st + cc * 16) =
            make_uint4(bpack(hi[0], hi[1]), bpack(hi[2], hi[3]),
                       bpack(hi[4], hi[5]), bpack(hi[6], hi[7]));
        *(uint4*)(alo_st + cc * 16) =
            make_uint4(bpack(lo[0], lo[1]), bpack(lo[2], lo[3]),
                       bpack(lo[4], lo[5]), bpack(lo[6], lo[7]));
      }
    } else {
      const uint4 z = make_uint4(0, 0, 0, 0);
#pragma unroll
      for (int cc = 0; cc < 8; cc++) {
        *(uint4*)(ahi_st + cc * 16) = z;
        *(uint4*)(alo_st + cc * 16) = z;
      }
    }
    __syncwarp();

    // ---- Phase B: 3-pass HMMA ----
    float acc[8][4];
#pragma unroll
    for (int n = 0; n < 8; n++)
#pragma unroll
      for (int q = 0; q < 4; q++) acc[n][q] = 0.f;

#pragma unroll
    for (int ks = 0; ks < 8; ks++) {
      // k-chunk ks covers channels ks*16..ks*16+15; second half starts at
      // byte HALF_OFF (144) instead of 128 -> +16 byte skew for ks>=4.
      const uint32_t kb = ks * 32 + ((ks >= 4) ? 16u : 0u);
      uint32_t ah0, ah1, ah2, ah3, al0, al1, al2, al3;
      LDSM4(ah0, ah1, ah2, ah3, ahi_ld + kb);
      LDSM4(al0, al1, al2, al3, alo_ld + kb);
      const uint2* bh = Bhi + ks * 256 + lane;
      const uint2* bl = Blo + ks * 256 + lane;
#pragma unroll
      for (int n = 0; n < 8; n++) {
        const uint2 vh = bh[n * 32];
        const uint2 vl = bl[n * 32];
        MMA16816(acc[n], ah0, ah1, ah2, ah3, vh.x, vh.y);
        MMA16816(acc[n], ah0, ah1, ah2, ah3, vl.x, vl.y);
        MMA16816(acc[n], al0, al1, al2, al3, vh.x, vh.y);
      }
    }

    // ---- Epilogue ----
    float s0 = 0.f, s1 = 0.f;
#pragma unroll
    for (int n = 0; n < 8; n++) {
      const int c0 = n * 8 + (lane & 3) * 2;
      const float b20 = b2s[c0], b21 = b2s[c0 + 1];
      const float w30 = w3s[c0], w31 = w3s[c0 + 1];
      s0 = fmaf(fmaxf(acc[n][0] + b20, 0.f), w30, s0);
      s0 = fmaf(fmaxf(acc[n][1] + b21, 0.f), w31, s0);
      s1 = fmaf(fmaxf(acc[n][2] + b20, 0.f), w30, s1);
      s1 = fmaf(fmaxf(acc[n][3] + b21, 0.f), w31, s1);
    }
    s0 += __shfl_xor_sync(0xffffffffu, s0, 1);
    s0 += __shfl_xor_sync(0xffffffffu, s0, 2);
    s1 += __shfl_xor_sync(0xffffffffu, s1, 1);
    s1 += __shfl_xor_sync(0xffffffffu, s1, 2);
    if ((lane & 3) == 0) {
      const int r0 = rbase + (lane >> 2);
      if (r0 < N) out[r0] = s0 + b3v;
      const int r1 = r0 + 8;
      if (r1 < N) out[r1] = s1 + b3v;
    }
    __syncwarp();   // protect smem tile reuse next iteration
  }
}

// ---------------------------------------------------------------------------
extern "C" void kernel_launch(void* const* d_in, const int* in_sizes, int n_in,
                              void* d_out, int out_size) {
  const int* indices = (const int*)d_in[0];
  // d_in[1] = nr (fixed 24)
  const float* x  = (const float*)d_in[2];
  const float* W1 = (const float*)d_in[3];
  const float* b1 = (const float*)d_in[4];
  const float* W2 = (const float*)d_in[5];
  const float* b2 = (const float*)d_in[6];
  const float* W3 = (const float*)d_in[7];
  const float* b3 = (const float*)d_in[8];
  float* out = (float*)d_out;

  const int N = in_sizes[0] / 23;          // 500000
  const int nodes = in_sizes[2] / 128;     // 10000
  const int G = (N - 2) / 25 + 1;          // 20000 groups

  cudaFuncSetAttribute(mlp_main_mma,
                       cudaFuncAttributeMaxDynamicSharedMemorySize, SMEM_BYTES);

  dim3 gridA((nodes + 31) / 32, 3);
  precompute_P<<<gridA, 128>>>(x, W1, nodes);
  group_ctx<<<G, 128>>>(indices, b1, G);
  mlp_main_mma<<<296, 256, SMEM_BYTES>>>(indices, W2, b2, W3, b3, out, N);
}

// round 7
// speedup vs baseline: 2.1408x; 1.2374x over previous
#include <cuda_runtime.h>
#include <cuda_bf16.h>
#include <cstdint>

#define NCAP 10240            // node capacity for P tables
#define GCAP 20032            // group capacity

// Scratch (device globals: no allocations allowed)
__device__ float g_P[3 * NCAP * 128];   // Pa | Pb | Pc, each [nodes][128]
__device__ float g_Gc[GCAP * 128];      // per-group ctx term (+ b1 folded)

// ---------------------------------------------------------------------------
// helpers
// ---------------------------------------------------------------------------
__device__ __forceinline__ uint32_t smem_u32(const void* p) {
  uint32_t a;
  asm("{ .reg .u64 t; cvta.to.shared.u64 t, %1; cvt.u32.u64 %0, t; }"
      : "=r"(a) : "l"(p));
  return a;
}

__device__ __forceinline__ uint32_t bpack(__nv_bfloat16 a, __nv_bfloat16 b) {
  __nv_bfloat162 t(a, b);          // .x = a (low half)
  return *reinterpret_cast<uint32_t*>(&t);
}

#define LDSM4(r0, r1, r2, r3, addr)                                          \
  asm volatile(                                                              \
      "ldmatrix.sync.aligned.m8n8.x4.shared.b16 {%0,%1,%2,%3}, [%4];"        \
      : "=r"(r0), "=r"(r1), "=r"(r2), "=r"(r3) : "r"(addr))

#define MMA16816(d, a0, a1, a2, a3, b0, b1)                                  \
  asm volatile(                                                              \
      "mma.sync.aligned.m16n8k16.row.col.f32.bf16.bf16.f32 "                 \
      "{%0,%1,%2,%3}, {%4,%5,%6,%7}, {%8,%9}, {%0,%1,%2,%3};"                \
      : "+f"((d)[0]), "+f"((d)[1]), "+f"((d)[2]), "+f"((d)[3])               \
      : "r"(a0), "r"(a1), "r"(a2), "r"(a3), "r"(b0), "r"(b1))

// truncate fp32 to bf16 (toward zero); exact residual in fp32
__device__ __forceinline__ float trunc_bf16(float v) {
  return __uint_as_float(__float_as_uint(v) & 0xffff0000u);
}

// ---------------------------------------------------------------------------
// Kernel A: P[part][n][j] = sum_k x[n][k] * W1[j][part*128 + k]
// 16 rows per block for higher resident-block count (grid-limited before)
// ---------------------------------------------------------------------------
__global__ __launch_bounds__(128) void precompute_P(
    const float* __restrict__ x, const float* __restrict__ W1, int nodes) {
  const int part = blockIdx.y;
  const int n0 = blockIdx.x * 16;
  __shared__ float xs[16 * 128];

  for (int i = threadIdx.x; i < 16 * 32; i += 128) {   // float4 units
    int n = i >> 5, c4 = i & 31;
    float4 v = make_float4(0.f, 0.f, 0.f, 0.f);
    if (n0 + n < nodes) v = ((const float4*)(x + (size_t)(n0 + n) * 128))[c4];
    ((float4*)(xs + n * 128))[c4] = v;
  }
  __syncthreads();

  const int j = threadIdx.x;
  const float* wrow = W1 + (size_t)j * 384 + part * 128;
  float acc[16];
#pragma unroll
  for (int n = 0; n < 16; n++) acc[n] = 0.f;

  for (int k = 0; k < 128; k += 4) {
    const float4 w = *(const float4*)(wrow + k);
#pragma unroll
    for (int n = 0; n < 16; n++) {
      const float4 xv = *(const float4*)(xs + n * 128 + k);
      float a = acc[n];
      a = fmaf(w.x, xv.x, a);
      a = fmaf(w.y, xv.y, a);
      a = fmaf(w.z, xv.z, a);
      a = fmaf(w.w, xv.w, a);
      acc[n] = a;
    }
  }

  float* Pp = g_P + (size_t)part * NCAP * 128;
#pragma unroll
  for (int n = 0; n < 16; n++)
    if (n0 + n < nodes) Pp[(size_t)(n0 + n) * 128 + j] = acc[n];
}

// ---------------------------------------------------------------------------
// Kernel B: per-group context term (+ b1 folded in)
// ---------------------------------------------------------------------------
__global__ __launch_bounds__(128) void group_ctx(
    const int* __restrict__ indices, const float* __restrict__ b1, int G) {
  const int g = blockIdx.x;
  if (g >= G) return;
  const int t = threadIdx.x;
  const int* ip = indices + (size_t)g * 25 * 23 + 3;
  const float* Pc = g_P + (size_t)2 * NCAP * 128;

  float s = 0.f;
  int cnt = 0;
#pragma unroll
  for (int kk = 0; kk < 20; kk++) {
    const int id = ip[kk];
    s += Pc[(size_t)id * 128 + t];
    cnt += (id > 0) ? 1 : 0;
  }
  const float norm = (float)(cnt > 0 ? cnt : 1);
  g_Gc[(size_t)g * 128 + t] = s / norm + b1[t];
}

// ---------------------------------------------------------------------------
// Kernel C: warp-independent HMMA MLP. Each warp owns a 16-row tile.
//  Phase A: line-aligned gather (lane = row*8lane-groups covering whole 128B
//           lines), relu, truncation hi/lo bf16 split into padded smem rows.
//           Row layout: k 0..63 at bytes [0,128), k 64..127 at bytes [144,272)
//  Phase B: 3-pass mma.sync m16n8k16 bf16 (Ahi*Bhi + Ahi*Blo + Alo*Bhi)
//  Epi:     out = relu(D + b2) . W3 + b3   (register-resident, shfl reduce)
// ---------------------------------------------------------------------------
#define AROW 272                       // bytes per h1 row (16-aligned halves)
#define HALF_OFF 144                   // byte offset of channels 64..127
#define AHI_OFF 0
#define ALO_OFF (8 * 16 * AROW)        // 34816
#define BF_OFF (2 * (8 * 16 * AROW))   // 69632
#define BFRAG_N 2048                   // (8 ks * 32 lanes * 8 n) uint2 per pass
#define MISC_OFF (BF_OFF + 2 * BFRAG_N * 8)  // 102400
#define SMEM_BYTES (MISC_OFF + 768)

__global__ void __launch_bounds__(256, 2) mlp_main_mma(
    const int* __restrict__ indices,
    const float* __restrict__ W2, const float* __restrict__ b2,
    const float* __restrict__ W3, const float* __restrict__ b3,
    float* __restrict__ out, int N) {
  extern __shared__ char smem[];
  const uint32_t sbase = smem_u32(smem);

  const int tid = threadIdx.x;
  const int wid = tid >> 5;
  const int lane = tid & 31;

  uint2* Bhi = (uint2*)(smem + BF_OFF);
  uint2* Blo = Bhi + BFRAG_N;
  float* b2s = (float*)(smem + MISC_OFF);
  float* w3s = b2s + 64;

  // ---- Build W2 bf16 hi/lo B-fragments (layout: [ks][lane][n] uint2) ----
  for (int i = tid; i < BFRAG_N; i += 256) {
    const int n = i & 7;
    const int ln = (i >> 3) & 31;
    const int ks = i >> 8;
    const int ng = n * 8 + (ln >> 2);          // output channel 0..63
    const int k0 = ks * 16 + (ln & 3) * 2;     // k of b0 pair
    const float* wr = W2 + (size_t)ng * 128 + k0;
    const float w00 = wr[0], w01 = wr[1], w10 = wr[8], w11 = wr[9];
    __nv_bfloat16 h00 = __float2bfloat16(w00);
    __nv_bfloat16 h01 = __float2bfloat16(w01);
    __nv_bfloat16 h10 = __float2bfloat16(w10);
    __nv_bfloat16 h11 = __float2bfloat16(w11);
    __nv_bfloat16 l00 = __float2bfloat16(w00 - __bfloat162float(h00));
    __nv_bfloat16 l01 = __float2bfloat16(w01 - __bfloat162float(h01));
    __nv_bfloat16 l10 = __float2bfloat16(w10 - __bfloat162float(h10));
    __nv_bfloat16 l11 = __float2bfloat16(w11 - __bfloat162float(h11));
    Bhi[i] = make_uint2(bpack(h00, h01), bpack(h10, h11));
    Blo[i] = make_uint2(bpack(l00, l01), bpack(l10, l11));
  }
  if (tid < 64) { b2s[tid] = b2[tid]; w3s[tid] = W3[tid]; }
  const float b3v = b3[0];
  __syncthreads();

  const float* Pa = g_P;
  const float* Pb = g_P + (size_t)NCAP * 128;

  // Phase-A line-aligned mapping: lane -> (row-in-quad rgl, 16B sub-block sub)
  const int sub = lane & 7;          // 16B sub-block within a 128B line
  const int rgl = lane >> 3;         // row within group of 4
  char* tile_hi = smem + AHI_OFF + (size_t)(wid * 16) * AROW;
  char* tile_lo = smem + ALO_OFF + (size_t)(wid * 16) * AROW;

  // ldmatrix addressing: lane -> (row, col-block)
  const uint32_t lrow = (lane < 16) ? lane : (lane - 16);
  const uint32_t lcol = (lane < 16) ? 0u : 16u;   // +8 cols in bytes
  const uint32_t ahi_ld = sbase + AHI_OFF + (wid * 16 + lrow) * AROW + lcol;
  const uint32_t alo_ld = sbase + ALO_OFF + (wid * 16 + lrow) * AROW + lcol;

  const int NTW = (N + 15) >> 4;
  const int wstride = gridDim.x * 8;

  for (int wt = blockIdx.x * 8 + wid; wt < NTW; wt += wstride) {
    const int rbase = wt << 4;

    // ---- Phase A: gather + relu + truncation bf16 hi/lo split ----
#pragma unroll
    for (int rg = 0; rg < 4; rg++) {
      const int r = rg * 4 + rgl;
      // clamp tail rows: the gathered data computes a value that is simply
      // never stored (outputs are row-guarded), so clamping is safe.
      const int gr = min(rbase + r, N - 1);
      const int i0 = indices[(size_t)gr * 23 + 0];
      const int i1 = indices[(size_t)gr * 23 + 1];
      const int g = gr / 25;
      const float* pa = Pa + (size_t)i0 * 128;
      const float* pb = Pb + (size_t)i1 * 128;
      const float* gc = g_Gc + (size_t)g * 128;
      char* rhi = tile_hi + (size_t)r * AROW;
      char* rlo = tile_lo + (size_t)r * AROW;
#pragma unroll
      for (int q = 0; q < 4; q++) {
        const int c = q * 32 + sub * 4;
        const float4 va = *(const float4*)(pa + c);
        const float4 vb = *(const float4*)(pb + c);
        const float4 vg = *(const float4*)(gc + c);
        float v0 = fmaxf(va.x + vb.x + vg.x, 0.f);
        float v1 = fmaxf(va.y + vb.y + vg.y, 0.f);
        float v2 = fmaxf(va.z + vb.z + vg.z, 0.f);
        float v3 = fmaxf(va.w + vb.w + vg.w, 0.f);
        // hi: truncated bf16 pair via PRMT; lo: exact residual, RN pack
        const uint32_t hi01 =
            __byte_perm(__float_as_uint(v0), __float_as_uint(v1), 0x7632);
        const uint32_t hi23 =
            __byte_perm(__float_as_uint(v2), __float_as_uint(v3), 0x7632);
        const float l0 = v0 - trunc_bf16(v0);
        const float l1 = v1 - trunc_bf16(v1);
        const float l2 = v2 - trunc_bf16(v2);
        const float l3 = v3 - trunc_bf16(v3);
        const __nv_bfloat162 lp01 = __floats2bfloat162_rn(l0, l1);
        const __nv_bfloat162 lp23 = __floats2bfloat162_rn(l2, l3);
        const int qb = (q < 2) ? (q * 64 + sub * 8)
                               : (HALF_OFF + (q - 2) * 64 + sub * 8);
        *(uint2*)(rhi + qb) = make_uint2(hi01, hi23);
        *(uint2*)(rlo + qb) =
            make_uint2(*(const uint32_t*)&lp01, *(const uint32_t*)&lp23);
      }
    }
    __syncwarp();

    // ---- Phase B: 3-pass HMMA ----
    float acc[8][4];
#pragma unroll
    for (int n = 0; n < 8; n++)
#pragma unroll
      for (int q = 0; q < 4; q++) acc[n][q] = 0.f;

#pragma unroll
    for (int ks = 0; ks < 8; ks++) {
      // k-chunk ks covers channels ks*16..ks*16+15; second half starts at
      // byte HALF_OFF (144) instead of 128 -> +16 byte skew for ks>=4.
      const uint32_t kb = ks * 32 + ((ks >= 4) ? 16u : 0u);
      uint32_t ah0, ah1, ah2, ah3, al0, al1, al2, al3;
      LDSM4(ah0, ah1, ah2, ah3, ahi_ld + kb);
      LDSM4(al0, al1, al2, al3, alo_ld + kb);
      const uint4* bh4 = (const uint4*)(Bhi + ((ks * 32 + lane) << 3));
      const uint4* bl4 = (const uint4*)(Blo + ((ks * 32 + lane) << 3));
#pragma unroll
      for (int np = 0; np < 4; np++) {
        const uint4 vh = bh4[np];    // n=2np (x,y), n=2np+1 (z,w)
        const uint4 vl = bl4[np];
        MMA16816(acc[2 * np], ah0, ah1, ah2, ah3, vh.x, vh.y);
        MMA16816(acc[2 * np], ah0, ah1, ah2, ah3, vl.x, vl.y);
        MMA16816(acc[2 * np], al0, al1, al2, al3, vh.x, vh.y);
        MMA16816(acc[2 * np + 1], ah0, ah1, ah2, ah3, vh.z, vh.w);
        MMA16816(acc[2 * np + 1], ah0, ah1, ah2, ah3, vl.z, vl.w);
        MMA16816(acc[2 * np + 1], al0, al1, al2, al3, vh.z, vh.w);
      }
    }

    // ---- Epilogue ----
    float s0 = 0.f, s1 = 0.f;
#pragma unroll
    for (int n = 0; n < 8; n++) {
      const int c0 = n * 8 + (lane & 3) * 2;
      const float2 b2p = *(const float2*)(b2s + c0);
      const float2 w3p = *(const float2*)(w3s + c0);
      s0 = fmaf(fmaxf(acc[n][0] + b2p.x, 0.f), w3p.x, s0);
      s0 = fmaf(fmaxf(acc[n][1] + b2p.y, 0.f), w3p.y, s0);
      s1 = fmaf(fmaxf(acc[n][2] + b2p.x, 0.f), w3p.x, s1);
      s1 = fmaf(fmaxf(acc[n][3] + b2p.y, 0.f), w3p.y, s1);
    }
    s0 += __shfl_xor_sync(0xffffffffu, s0, 1);
    s0 += __shfl_xor_sync(0xffffffffu, s0, 2);
    s1 += __shfl_xor_sync(0xffffffffu, s1, 1);
    s1 += __shfl_xor_sync(0xffffffffu, s1, 2);
    if ((lane & 3) == 0) {
      const int r0 = rbase + (lane >> 2);
      if (r0 < N) out[r0] = s0 + b3v;
      const int r1 = r0 + 8;
      if (r1 < N) out[r1] = s1 + b3v;
    }
    __syncwarp();   // protect smem tile reuse next iteration
  }
}

// ---------------------------------------------------------------------------
extern "C" void kernel_launch(void* const* d_in, const int* in_sizes, int n_in,
                              void* d_out, int out_size) {
  const int* indices = (const int*)d_in[0];
  // d_in[1] = nr (fixed 24)
  const float* x  = (const float*)d_in[2];
  const float* W1 = (const float*)d_in[3];
  const float* b1 = (const float*)d_in[4];
  const float* W2 = (const float*)d_in[5];
  const float* b2 = (const float*)d_in[6];
  const float* W3 = (const float*)d_in[7];
  const float* b3 = (const float*)d_in[8];
  float* out = (float*)d_out;

  const int N = in_sizes[0] / 23;          // 500000
  const int nodes = in_sizes[2] / 128;     // 10000
  const int G = (N - 2) / 25 + 1;          // 20000 groups

  cudaFuncSetAttribute(mlp_main_mma,
                       cudaFuncAttributeMaxDynamicSharedMemorySize, SMEM_BYTES);

  dim3 gridA((nodes + 15) / 16, 3);
  precompute_P<<<gridA, 128>>>(x, W1, nodes);
  group_ctx<<<G, 128>>>(indices, b1, G);
  mlp_main_mma<<<296, 256, SMEM_BYTES>>>(indices, W2, b2, W3, b3, out, N);
}

// round 8
// speedup vs baseline: 3.4072x; 1.5915x over previous
#include <cuda_runtime.h>
#include <cuda_bf16.h>
#include <cstdint>

#define NCAP 10240            // node capacity for P tables
#define GCAP 20032            // group capacity

// Scratch (device globals: no allocations allowed)
__device__ float g_P[3 * NCAP * 128];   // Pa | Pb | Pc, each [nodes][128]
__device__ float g_Gc[GCAP * 128];      // per-group ctx term (+ b1 folded)

// ---------------------------------------------------------------------------
// helpers
// ---------------------------------------------------------------------------
__device__ __forceinline__ uint32_t smem_u32(const void* p) {
  uint32_t a;
  asm("{ .reg .u64 t; cvta.to.shared.u64 t, %1; cvt.u32.u64 %0, t; }"
      : "=r"(a) : "l"(p));
  return a;
}

__device__ __forceinline__ uint32_t bpack(__nv_bfloat16 a, __nv_bfloat16 b) {
  __nv_bfloat162 t(a, b);          // .x = a (low half)
  return *reinterpret_cast<uint32_t*>(&t);
}

#define LDSM4(r0, r1, r2, r3, addr)                                          \
  asm volatile(                                                              \
      "ldmatrix.sync.aligned.m8n8.x4.shared.b16 {%0,%1,%2,%3}, [%4];"        \
      : "=r"(r0), "=r"(r1), "=r"(r2), "=r"(r3) : "r"(addr))

#define MMA16816(d, a0, a1, a2, a3, b0, b1)                                  \
  asm volatile(                                                              \
      "mma.sync.aligned.m16n8k16.row.col.f32.bf16.bf16.f32 "                 \
      "{%0,%1,%2,%3}, {%4,%5,%6,%7}, {%8,%9}, {%0,%1,%2,%3};"                \
      : "+f"((d)[0]), "+f"((d)[1]), "+f"((d)[2]), "+f"((d)[3])               \
      : "r"(a0), "r"(a1), "r"(a2), "r"(a3), "r"(b0), "r"(b1))

// truncate fp32 to bf16 (toward zero); exact residual in fp32
__device__ __forceinline__ float trunc_bf16(float v) {
  return __uint_as_float(__float_as_uint(v) & 0xffff0000u);
}

// ---------------------------------------------------------------------------
// Kernel A: P[part][n][j] = sum_k x[n][k] * W1[j][part*128 + k]
// One thread computes ALL 3 parts for its j: each xs smem read feeds 3 FMA
// chains (kernel was LDS-issue-bound; this triples FMA per LDS).
// grid: ceil(nodes/16), block: 128 (thread = output channel j)
// ---------------------------------------------------------------------------
__global__ __launch_bounds__(128) void precompute_P(
    const float* __restrict__ x, const float* __restrict__ W1, int nodes) {
  const int n0 = blockIdx.x * 16;
  __shared__ float xs[16 * 128];

  for (int i = threadIdx.x; i < 16 * 32; i += 128) {   // float4 units
    int n = i >> 5, c4 = i & 31;
    float4 v = make_float4(0.f, 0.f, 0.f, 0.f);
    if (n0 + n < nodes) v = ((const float4*)(x + (size_t)(n0 + n) * 128))[c4];
    ((float4*)(xs + n * 128))[c4] = v;
  }
  __syncthreads();

  const int j = threadIdx.x;
  const float* wrow = W1 + (size_t)j * 384;
  float acc0[16], acc1[16], acc2[16];
#pragma unroll
  for (int n = 0; n < 16; n++) { acc0[n] = 0.f; acc1[n] = 0.f; acc2[n] = 0.f; }

  for (int k = 0; k < 128; k += 4) {
    const float4 w0 = *(const float4*)(wrow + k);
    const float4 w1 = *(const float4*)(wrow + 128 + k);
    const float4 w2 = *(const float4*)(wrow + 256 + k);
#pragma unroll
    for (int n = 0; n < 16; n++) {
      const float4 xv = *(const float4*)(xs + n * 128 + k);
      float a0 = acc0[n], a1 = acc1[n], a2 = acc2[n];
      a0 = fmaf(w0.x, xv.x, a0); a0 = fmaf(w0.y, xv.y, a0);
      a0 = fmaf(w0.z, xv.z, a0); a0 = fmaf(w0.w, xv.w, a0);
      a1 = fmaf(w1.x, xv.x, a1); a1 = fmaf(w1.y, xv.y, a1);
      a1 = fmaf(w1.z, xv.z, a1); a1 = fmaf(w1.w, xv.w, a1);
      a2 = fmaf(w2.x, xv.x, a2); a2 = fmaf(w2.y, xv.y, a2);
      a2 = fmaf(w2.z, xv.z, a2); a2 = fmaf(w2.w, xv.w, a2);
      acc0[n] = a0; acc1[n] = a1; acc2[n] = a2;
    }
  }

#pragma unroll
  for (int n = 0; n < 16; n++) {
    if (n0 + n < nodes) {
      const size_t ro = (size_t)(n0 + n) * 128 + j;
      g_P[ro] = acc0[n];
      g_P[(size_t)NCAP * 128 + ro] = acc1[n];
      g_P[(size_t)2 * NCAP * 128 + ro] = acc2[n];
    }
  }
}

// ---------------------------------------------------------------------------
// Kernel B: per-group context term (+ b1 folded in)
// ---------------------------------------------------------------------------
__global__ __launch_bounds__(128) void group_ctx(
    const int* __restrict__ indices, const float* __restrict__ b1, int G) {
  const int g = blockIdx.x;
  if (g >= G) return;
  const int t = threadIdx.x;
  const int* ip = indices + (size_t)g * 25 * 23 + 3;
  const float* Pc = g_P + (size_t)2 * NCAP * 128;

  float s = 0.f;
  int cnt = 0;
#pragma unroll
  for (int kk = 0; kk < 20; kk++) {
    const int id = ip[kk];
    s += Pc[(size_t)id * 128 + t];
    cnt += (id > 0) ? 1 : 0;
  }
  const float norm = (float)(cnt > 0 ? cnt : 1);
  g_Gc[(size_t)g * 128 + t] = s / norm + b1[t];
}

// ---------------------------------------------------------------------------
// Kernel C: warp-independent HMMA MLP. Each warp owns a 16-row tile.
//  Phase A: line-aligned gather, relu, truncation hi/lo bf16 split.
//           Row layout: k 0..63 at bytes [0,128), k 64..127 at bytes [144,272)
//  Phase B: 3-pass mma.sync m16n8k16 bf16 (Ahi*Bhi + Ahi*Blo + Alo*Bhi)
//           B fragments laid out [ks][np][lane] (uint4) -> conflict-free LDS.128
//  Epi:     out = relu(D + b2) . W3 + b3   (register-resident, shfl reduce)
// ---------------------------------------------------------------------------
#define AROW 272                       // bytes per h1 row (16-aligned halves)
#define HALF_OFF 144                   // byte offset of channels 64..127
#define AHI_OFF 0
#define ALO_OFF (8 * 16 * AROW)        // 34816
#define BF_OFF (2 * (8 * 16 * AROW))   // 69632
#define BFRAG_U4 1024                  // (8 ks * 4 np * 32 lanes) uint4 per pass
#define MISC_OFF (BF_OFF + 2 * BFRAG_U4 * 16)  // 102400
#define SMEM_BYTES (MISC_OFF + 768)

__global__ void __launch_bounds__(256, 2) mlp_main_mma(
    const int* __restrict__ indices,
    const float* __restrict__ W2, const float* __restrict__ b2,
    const float* __restrict__ W3, const float* __restrict__ b3,
    float* __restrict__ out, int N) {
  extern __shared__ char smem[];
  const uint32_t sbase = smem_u32(smem);

  const int tid = threadIdx.x;
  const int wid = tid >> 5;
  const int lane = tid & 31;

  uint4* Bhi4 = (uint4*)(smem + BF_OFF);     // [ks][np][lane]
  uint4* Blo4 = Bhi4 + BFRAG_U4;
  float* b2s = (float*)(smem + MISC_OFF);
  float* w3s = b2s + 64;

  // ---- Build W2 bf16 hi/lo B-fragments: uint4 i = ((ks*4+np)*32 + lane)
  //      holds frags for n = 2np (x,y) and n = 2np+1 (z,w). ----
  for (int i = tid; i < BFRAG_U4; i += 256) {
    const int ln = i & 31;
    const int np = (i >> 5) & 3;
    const int ks = i >> 7;
    uint32_t hx[2], hy[2], lx[2], ly[2];
#pragma unroll
    for (int t = 0; t < 2; t++) {
      const int nn = 2 * np + t;
      const int ng = nn * 8 + (ln >> 2);         // output channel 0..63
      const int k0 = ks * 16 + (ln & 3) * 2;     // k of b0 pair
      const float* wr = W2 + (size_t)ng * 128 + k0;
      const float w00 = wr[0], w01 = wr[1], w10 = wr[8], w11 = wr[9];
      __nv_bfloat16 h00 = __float2bfloat16(w00);
      __nv_bfloat16 h01 = __float2bfloat16(w01);
      __nv_bfloat16 h10 = __float2bfloat16(w10);
      __nv_bfloat16 h11 = __float2bfloat16(w11);
      __nv_bfloat16 l00 = __float2bfloat16(w00 - __bfloat162float(h00));
      __nv_bfloat16 l01 = __float2bfloat16(w01 - __bfloat162float(h01));
      __nv_bfloat16 l10 = __float2bfloat16(w10 - __bfloat162float(h10));
      __nv_bfloat16 l11 = __float2bfloat16(w11 - __bfloat162float(h11));
      hx[t] = bpack(h00, h01); hy[t] = bpack(h10, h11);
      lx[t] = bpack(l00, l01); ly[t] = bpack(l10, l11);
    }
    Bhi4[i] = make_uint4(hx[0], hy[0], hx[1], hy[1]);
    Blo4[i] = make_uint4(lx[0], ly[0], lx[1], ly[1]);
  }
  if (tid < 64) { b2s[tid] = b2[tid]; w3s[tid] = W3[tid]; }
  const float b3v = b3[0];
  __syncthreads();

  const float* Pa = g_P;
  const float* Pb = g_P + (size_t)NCAP * 128;

  // Phase-A line-aligned mapping: lane -> (row-in-quad rgl, 16B sub-block sub)
  const int sub = lane & 7;          // 16B sub-block within a 128B line
  const int rgl = lane >> 3;         // row within group of 4
  char* tile_hi = smem + AHI_OFF + (size_t)(wid * 16) * AROW;
  char* tile_lo = smem + ALO_OFF + (size_t)(wid * 16) * AROW;

  // ldmatrix addressing: lane -> (row, col-block)
  const uint32_t lrow = (lane < 16) ? lane : (lane - 16);
  const uint32_t lcol = (lane < 16) ? 0u : 16u;   // +8 cols in bytes
  const uint32_t ahi_ld = sbase + AHI_OFF + (wid * 16 + lrow) * AROW + lcol;
  const uint32_t alo_ld = sbase + ALO_OFF + (wid * 16 + lrow) * AROW + lcol;

  const int NTW = (N + 15) >> 4;
  const int wstride = gridDim.x * 8;

  for (int wt = blockIdx.x * 8 + wid; wt < NTW; wt += wstride) {
    const int rbase = wt << 4;

    // ---- Phase A: gather + relu + truncation bf16 hi/lo split ----
#pragma unroll
    for (int rg = 0; rg < 4; rg++) {
      const int r = rg * 4 + rgl;
      // clamp tail rows: gathered value is simply never stored to out
      const int gr = min(rbase + r, N - 1);
      const int i0 = indices[(size_t)gr * 23 + 0];
      const int i1 = indices[(size_t)gr * 23 + 1];
      const int g = gr / 25;
      const float* pa = Pa + (size_t)i0 * 128;
      const float* pb = Pb + (size_t)i1 * 128;
      const float* gc = g_Gc + (size_t)g * 128;
      char* rhi = tile_hi + (size_t)r * AROW;
      char* rlo = tile_lo + (size_t)r * AROW;
#pragma unroll
      for (int q = 0; q < 4; q++) {
        const int c = q * 32 + sub * 4;
        const float4 va = *(const float4*)(pa + c);
        const float4 vb = *(const float4*)(pb + c);
        const float4 vg = *(const float4*)(gc + c);
        float v0 = fmaxf(va.x + vb.x + vg.x, 0.f);
        float v1 = fmaxf(va.y + vb.y + vg.y, 0.f);
        float v2 = fmaxf(va.z + vb.z + vg.z, 0.f);
        float v3 = fmaxf(va.w + vb.w + vg.w, 0.f);
        // hi: truncated bf16 pair via PRMT; lo: exact residual, RN pack
        const uint32_t hi01 =
            __byte_perm(__float_as_uint(v0), __float_as_uint(v1), 0x7632);
        const uint32_t hi23 =
            __byte_perm(__float_as_uint(v2), __float_as_uint(v3), 0x7632);
        const float l0 = v0 - trunc_bf16(v0);
        const float l1 = v1 - trunc_bf16(v1);
        const float l2 = v2 - trunc_bf16(v2);
        const float l3 = v3 - trunc_bf16(v3);
        const __nv_bfloat162 lp01 = __floats2bfloat162_rn(l0, l1);
        const __nv_bfloat162 lp23 = __floats2bfloat162_rn(l2, l3);
        const int qb = (q < 2) ? (q * 64 + sub * 8)
                               : (HALF_OFF + (q - 2) * 64 + sub * 8);
        *(uint2*)(rhi + qb) = make_uint2(hi01, hi23);
        *(uint2*)(rlo + qb) =
            make_uint2(*(const uint32_t*)&lp01, *(const uint32_t*)&lp23);
      }
    }
    __syncwarp();

    // ---- Phase B: 3-pass HMMA ----
    float acc[8][4];
#pragma unroll
    for (int n = 0; n < 8; n++)
#pragma unroll
      for (int q = 0; q < 4; q++) acc[n][q] = 0.f;

#pragma unroll
    for (int ks = 0; ks < 8; ks++) {
      // k-chunk ks covers channels ks*16..ks*16+15; second half starts at
      // byte HALF_OFF (144) instead of 128 -> +16 byte skew for ks>=4.
      const uint32_t kb = ks * 32 + ((ks >= 4) ? 16u : 0u);
      uint32_t ah0, ah1, ah2, ah3, al0, al1, al2, al3;
      LDSM4(ah0, ah1, ah2, ah3, ahi_ld + kb);
      LDSM4(al0, al1, al2, al3, alo_ld + kb);
#pragma unroll
      for (int np = 0; np < 4; np++) {
        const uint4 vh = Bhi4[(ks * 4 + np) * 32 + lane];
        const uint4 vl = Blo4[(ks * 4 + np) * 32 + lane];
        MMA16816(acc[2 * np], ah0, ah1, ah2, ah3, vh.x, vh.y);
        MMA16816(acc[2 * np], ah0, ah1, ah2, ah3, vl.x, vl.y);
        MMA16816(acc[2 * np], al0, al1, al2, al3, vh.x, vh.y);
        MMA16816(acc[2 * np + 1], ah0, ah1, ah2, ah3, vh.z, vh.w);
        MMA16816(acc[2 * np + 1], ah0, ah1, ah2, ah3, vl.z, vl.w);
        MMA16816(acc[2 * np + 1], al0, al1, al2, al3, vh.z, vh.w);
      }
    }

    // ---- Epilogue ----
    float s0 = 0.f, s1 = 0.f;
#pragma unroll
    for (int n = 0; n < 8; n++) {
      const int c0 = n * 8 + (lane & 3) * 2;
      const float2 b2p = *(const float2*)(b2s + c0);
      const float2 w3p = *(const float2*)(w3s + c0);
      s0 = fmaf(fmaxf(acc[n][0] + b2p.x, 0.f), w3p.x, s0);
      s0 = fmaf(fmaxf(acc[n][1] + b2p.y, 0.f), w3p.y, s0);
      s1 = fmaf(fmaxf(acc[n][2] + b2p.x, 0.f), w3p.x, s1);
      s1 = fmaf(fmaxf(acc[n][3] + b2p.y, 0.f), w3p.y, s1);
    }
    s0 += __shfl_xor_sync(0xffffffffu, s0, 1);
    s0 += __shfl_xor_sync(0xffffffffu, s0, 2);
    s1 += __shfl_xor_sync(0xffffffffu, s1, 1);
    s1 += __shfl_xor_sync(0xffffffffu, s1, 2);
    if ((lane & 3) == 0) {
      const int r0 = rbase + (lane >> 2);
      if (r0 < N) out[r0] = s0 + b3v;
      const int r1 = r0 + 8;
      if (r1 < N) out[r1] = s1 + b3v;
    }
    __syncwarp();   // protect smem tile reuse next iteration
  }
}

// ---------------------------------------------------------------------------
extern "C" void kernel_launch(void* const* d_in, const int* in_sizes, int n_in,
                              void* d_out, int out_size) {
  const int* indices = (const int*)d_in[0];
  // d_in[1] = nr (fixed 24)
  const float* x  = (const float*)d_in[2];
  const float* W1 = (const float*)d_in[3];
  const float* b1 = (const float*)d_in[4];
  const float* W2 = (const float*)d_in[5];
  const float* b2 = (const float*)d_in[6];
  const float* W3 = (const float*)d_in[7];
  const float* b3 = (const float*)d_in[8];
  float* out = (float*)d_out;

  const int N = in_sizes[0] / 23;          // 500000
  const int nodes = in_sizes[2] / 128;     // 10000
  const int G = (N - 2) / 25 + 1;          // 20000 groups

  cudaFuncSetAttribute(mlp_main_mma,
                       cudaFuncAttributeMaxDynamicSharedMemorySize, SMEM_BYTES);

  precompute_P<<<(nodes + 15) / 16, 128>>>(x, W1, nodes);
  group_ctx<<<G, 128>>>(indices, b1, G);
  mlp_main_mma<<<296, 256, SMEM_BYTES>>>(indices, W2, b2, W3, b3, out, N);
}

// round 9
// speedup vs baseline: 3.7552x; 1.1021x over previous
#include <cuda_runtime.h>
#include <cuda_bf16.h>
#include <cstdint>

#define NCAP 10240            // node capacity for P tables
#define GCAP 20032            // group capacity

// Scratch (device globals: no allocations allowed)
__device__ float g_P[3 * NCAP * 128];   // Pa | Pb | Pc, each [nodes][128]
__device__ float g_Gc[GCAP * 128];      // per-group ctx term (+ b1 folded)

// ---------------------------------------------------------------------------
// helpers
// ---------------------------------------------------------------------------
__device__ __forceinline__ uint32_t smem_u32(const void* p) {
  uint32_t a;
  asm("{ .reg .u64 t; cvta.to.shared.u64 t, %1; cvt.u32.u64 %0, t; }"
      : "=r"(a) : "l"(p));
  return a;
}

__device__ __forceinline__ uint32_t bpack(__nv_bfloat16 a, __nv_bfloat16 b) {
  __nv_bfloat162 t(a, b);          // .x = a (low half)
  return *reinterpret_cast<uint32_t*>(&t);
}

#define LDSM4(r0, r1, r2, r3, addr)                                          \
  asm volatile(                                                              \
      "ldmatrix.sync.aligned.m8n8.x4.shared.b16 {%0,%1,%2,%3}, [%4];"        \
      : "=r"(r0), "=r"(r1), "=r"(r2), "=r"(r3) : "r"(addr))

#define MMA16816(d, a0, a1, a2, a3, b0, b1)                                  \
  asm volatile(                                                              \
      "mma.sync.aligned.m16n8k16.row.col.f32.bf16.bf16.f32 "                 \
      "{%0,%1,%2,%3}, {%4,%5,%6,%7}, {%8,%9}, {%0,%1,%2,%3};"                \
      : "+f"((d)[0]), "+f"((d)[1]), "+f"((d)[2]), "+f"((d)[3])               \
      : "r"(a0), "r"(a1), "r"(a2), "r"(a3), "r"(b0), "r"(b1))

// truncate fp32 to bf16 (toward zero); exact residual in fp32
__device__ __forceinline__ float trunc_bf16(float v) {
  return __uint_as_float(__float_as_uint(v) & 0xffff0000u);
}

// Common A-tile geometry (shared by both MMA kernels)
#define AROW 272                       // bytes per 128-ch row (16-aligned halves)
#define HALF_OFF 144                   // byte offset of channels 64..127

// build one hi/lo B-fragment uint4 pair from two weight rows
__device__ __forceinline__ void build_bfrag(const float* w_base, int row_stride,
                                            int ng0, int ng1, int k0,
                                            uint4* hi, uint4* lo) {
  uint32_t hx[2], hy[2], lx[2], ly[2];
  const int ngs[2] = {ng0, ng1};
#pragma unroll
  for (int t = 0; t < 2; t++) {
    const float* wr = w_base + (size_t)ngs[t] * row_stride + k0;
    const float w00 = wr[0], w01 = wr[1], w10 = wr[8], w11 = wr[9];
    __nv_bfloat16 h00 = __float2bfloat16(w00);
    __nv_bfloat16 h01 = __float2bfloat16(w01);
    __nv_bfloat16 h10 = __float2bfloat16(w10);
    __nv_bfloat16 h11 = __float2bfloat16(w11);
    __nv_bfloat16 l00 = __float2bfloat16(w00 - __bfloat162float(h00));
    __nv_bfloat16 l01 = __float2bfloat16(w01 - __bfloat162float(h01));
    __nv_bfloat16 l10 = __float2bfloat16(w10 - __bfloat162float(h10));
    __nv_bfloat16 l11 = __float2bfloat16(w11 - __bfloat162float(h11));
    hx[t] = bpack(h00, h01); hy[t] = bpack(h10, h11);
    lx[t] = bpack(l00, l01); ly[t] = bpack(l10, l11);
  }
  *hi = make_uint4(hx[0], hy[0], hx[1], hy[1]);
  *lo = make_uint4(lx[0], ly[0], lx[1], ly[1]);
}

// ---------------------------------------------------------------------------
// Kernel A (tensor): P[p][n][j] = sum_k x[n][k] * W1[j][p*128+k]
// 157 blocks x 128 threads (4 warps). Each warp owns one 16-row x tile.
// Parts processed sequentially (B-frags rebuilt per part to fit smem).
// 3-pass trunc hi/lo bf16 split -> ~2^-17 relative accuracy on P.
// ---------------------------------------------------------------------------
#define PP_AHI 0
#define PP_ALO (4 * 16 * AROW)             // 17408
#define PP_BHI (2 * 4 * 16 * AROW)         // 34816
#define PP_BLO (PP_BHI + 32768)            // 67584
#define PP_SMEM (PP_BLO + 32768)           // 100352

__global__ void __launch_bounds__(128) precompute_P_tc(
    const float* __restrict__ x, const float* __restrict__ W1, int nodes) {
  extern __shared__ char smem[];
  const uint32_t sbase = smem_u32(smem);
  const int tid = threadIdx.x;
  const int wid = tid >> 5;
  const int lane = tid & 31;

  uint4* Bhi4 = (uint4*)(smem + PP_BHI);   // [ks][np][lane], np=0..7 (16 nf)
  uint4* Blo4 = (uint4*)(smem + PP_BLO);

  const int ntiles = (nodes + 15) >> 4;
  const int wt = blockIdx.x * 4 + wid;
  const bool active = (wt < ntiles);
  const int n0 = wt << 4;

  // ---- A split: 16 x-rows -> trunc hi/lo bf16 in AROW layout ----
  const int sub = lane & 7;
  const int rgl = lane >> 3;
  char* tile_hi = smem + PP_AHI + (size_t)wid * 16 * AROW;
  char* tile_lo = smem + PP_ALO + (size_t)wid * 16 * AROW;
  if (active) {
#pragma unroll
    for (int rg = 0; rg < 4; rg++) {
      const int r = rg * 4 + rgl;
      const int gr = min(n0 + r, nodes - 1);
      const float* xr = x + (size_t)gr * 128;
      char* rhi = tile_hi + (size_t)r * AROW;
      char* rlo = tile_lo + (size_t)r * AROW;
#pragma unroll
      for (int q = 0; q < 4; q++) {
        const int c = q * 32 + sub * 4;
        const float4 v4 = *(const float4*)(xr + c);
        const uint32_t hi01 = __byte_perm(__float_as_uint(v4.x),
                                          __float_as_uint(v4.y), 0x7632);
        const uint32_t hi23 = __byte_perm(__float_as_uint(v4.z),
                                          __float_as_uint(v4.w), 0x7632);
        const float l0 = v4.x - trunc_bf16(v4.x);
        const float l1 = v4.y - trunc_bf16(v4.y);
        const float l2 = v4.z - trunc_bf16(v4.z);
        const float l3 = v4.w - trunc_bf16(v4.w);
        const __nv_bfloat162 lp01 = __floats2bfloat162_rn(l0, l1);
        const __nv_bfloat162 lp23 = __floats2bfloat162_rn(l2, l3);
        const int qb = (q < 2) ? (q * 64 + sub * 8)
                               : (HALF_OFF + (q - 2) * 64 + sub * 8);
        *(uint2*)(rhi + qb) = make_uint2(hi01, hi23);
        *(uint2*)(rlo + qb) =
            make_uint2(*(const uint32_t*)&lp01, *(const uint32_t*)&lp23);
      }
    }
  }

  // ldmatrix addressing
  const uint32_t lrow = (lane < 16) ? lane : (lane - 16);
  const uint32_t lcol = (lane < 16) ? 0u : 16u;
  const uint32_t ahi_ld = sbase + PP_AHI + (wid * 16 + lrow) * AROW + lcol;
  const uint32_t alo_ld = sbase + PP_ALO + (wid * 16 + lrow) * AROW + lcol;

  for (int p = 0; p < 3; p++) {
    // ---- build B-frags for part p: W1[ng][p*128 + k] ----
    __syncthreads();   // also covers A-split completion on first pass
    for (int i = tid; i < 2048; i += 128) {
      const int ln = i & 31;
      const int np = (i >> 5) & 7;
      const int ks = i >> 8;
      const int k0 = ks * 16 + (ln & 3) * 2;
      const int ng0 = (2 * np) * 8 + (ln >> 2);
      const int ng1 = (2 * np + 1) * 8 + (ln >> 2);
      build_bfrag(W1 + p * 128, 384, ng0, ng1, k0, &Bhi4[i], &Blo4[i]);
    }
    __syncthreads();

    if (active) {
      float acc[16][4];
#pragma unroll
      for (int n = 0; n < 16; n++)
#pragma unroll
        for (int q = 0; q < 4; q++) acc[n][q] = 0.f;

#pragma unroll
      for (int ks = 0; ks < 8; ks++) {
        const uint32_t kb = ks * 32 + ((ks >= 4) ? 16u : 0u);
        uint32_t ah0, ah1, ah2, ah3, al0, al1, al2, al3;
        LDSM4(ah0, ah1, ah2, ah3, ahi_ld + kb);
        LDSM4(al0, al1, al2, al3, alo_ld + kb);
#pragma unroll
        for (int np = 0; np < 8; np++) {
          const uint4 vh = Bhi4[(ks * 8 + np) * 32 + lane];
          const uint4 vl = Blo4[(ks * 8 + np) * 32 + lane];
          MMA16816(acc[2 * np], ah0, ah1, ah2, ah3, vh.x, vh.y);
          MMA16816(acc[2 * np], ah0, ah1, ah2, ah3, vl.x, vl.y);
          MMA16816(acc[2 * np], al0, al1, al2, al3, vh.x, vh.y);
          MMA16816(acc[2 * np + 1], ah0, ah1, ah2, ah3, vh.z, vh.w);
          MMA16816(acc[2 * np + 1], ah0, ah1, ah2, ah3, vl.z, vl.w);
          MMA16816(acc[2 * np + 1], al0, al1, al2, al3, vh.z, vh.w);
        }
      }

      // store D -> g_P[p]; fragment mapping: rows lane>>2 and +8, cols nf*8+(lane&3)*2
      float* Pp = g_P + (size_t)p * NCAP * 128;
      const int r0 = n0 + (lane >> 2);
      const int r1 = r0 + 8;
#pragma unroll
      for (int nf = 0; nf < 16; nf++) {
        const int c0 = nf * 8 + (lane & 3) * 2;
        if (r0 < nodes)
          *(float2*)(Pp + (size_t)r0 * 128 + c0) = make_float2(acc[nf][0], acc[nf][1]);
        if (r1 < nodes)
          *(float2*)(Pp + (size_t)r1 * 128 + c0) = make_float2(acc[nf][2], acc[nf][3]);
      }
    }
    __syncthreads();   // protect B-frag region before next part's build
  }
}

// ---------------------------------------------------------------------------
// Kernel B: per-group context term (+ b1 folded in)
// ---------------------------------------------------------------------------
__global__ __launch_bounds__(128) void group_ctx(
    const int* __restrict__ indices, const float* __restrict__ b1, int G) {
  const int g = blockIdx.x;
  if (g >= G) return;
  const int t = threadIdx.x;
  const int* ip = indices + (size_t)g * 25 * 23 + 3;
  const float* Pc = g_P + (size_t)2 * NCAP * 128;

  float s = 0.f;
  int cnt = 0;
#pragma unroll
  for (int kk = 0; kk < 20; kk++) {
    const int id = ip[kk];
    s += Pc[(size_t)id * 128 + t];
    cnt += (id > 0) ? 1 : 0;
  }
  const float norm = (float)(cnt > 0 ? cnt : 1);
  g_Gc[(size_t)g * 128 + t] = s / norm + b1[t];
}

// ---------------------------------------------------------------------------
// Kernel C: warp-independent HMMA MLP. Each warp owns a 16-row tile.
// ---------------------------------------------------------------------------
#define AHI_OFF 0
#define ALO_OFF (8 * 16 * AROW)        // 34816
#define BF_OFF (2 * (8 * 16 * AROW))   // 69632
#define BFRAG_U4 1024                  // (8 ks * 4 np * 32 lanes) uint4 per pass
#define MISC_OFF (BF_OFF + 2 * BFRAG_U4 * 16)  // 102400
#define SMEM_BYTES (MISC_OFF + 768)

__global__ void __launch_bounds__(256, 2) mlp_main_mma(
    const int* __restrict__ indices,
    const float* __restrict__ W2, const float* __restrict__ b2,
    const float* __restrict__ W3, const float* __restrict__ b3,
    float* __restrict__ out, int N) {
  extern __shared__ char smem[];
  const uint32_t sbase = smem_u32(smem);

  const int tid = threadIdx.x;
  const int wid = tid >> 5;
  const int lane = tid & 31;

  uint4* Bhi4 = (uint4*)(smem + BF_OFF);     // [ks][np][lane]
  uint4* Blo4 = Bhi4 + BFRAG_U4;
  float* b2s = (float*)(smem + MISC_OFF);
  float* w3s = b2s + 64;

  // ---- Build W2 bf16 hi/lo B-fragments ----
  for (int i = tid; i < BFRAG_U4; i += 256) {
    const int ln = i & 31;
    const int np = (i >> 5) & 3;
    const int ks = i >> 7;
    const int k0 = ks * 16 + (ln & 3) * 2;
    const int ng0 = (2 * np) * 8 + (ln >> 2);
    const int ng1 = (2 * np + 1) * 8 + (ln >> 2);
    build_bfrag(W2, 128, ng0, ng1, k0, &Bhi4[i], &Blo4[i]);
  }
  if (tid < 64) { b2s[tid] = b2[tid]; w3s[tid] = W3[tid]; }
  const float b3v = b3[0];
  __syncthreads();

  const float* Pa = g_P;
  const float* Pb = g_P + (size_t)NCAP * 128;

  const int sub = lane & 7;          // 16B sub-block within a 128B line
  const int rgl = lane >> 3;         // row within group of 4
  char* tile_hi = smem + AHI_OFF + (size_t)(wid * 16) * AROW;
  char* tile_lo = smem + ALO_OFF + (size_t)(wid * 16) * AROW;

  const uint32_t lrow = (lane < 16) ? lane : (lane - 16);
  const uint32_t lcol = (lane < 16) ? 0u : 16u;
  const uint32_t ahi_ld = sbase + AHI_OFF + (wid * 16 + lrow) * AROW + lcol;
  const uint32_t alo_ld = sbase + ALO_OFF + (wid * 16 + lrow) * AROW + lcol;

  const int NTW = (N + 15) >> 4;
  const int wstride = gridDim.x * 8;

  for (int wt = blockIdx.x * 8 + wid; wt < NTW; wt += wstride) {
    const int rbase = wt << 4;

    // ---- Phase A: gather + relu + truncation bf16 hi/lo split ----
#pragma unroll
    for (int rg = 0; rg < 4; rg++) {
      const int r = rg * 4 + rgl;
      const int gr = min(rbase + r, N - 1);
      const int i0 = indices[(size_t)gr * 23 + 0];
      const int i1 = indices[(size_t)gr * 23 + 1];
      const int g = gr / 25;
      const float* pa = Pa + (size_t)i0 * 128;
      const float* pb = Pb + (size_t)i1 * 128;
      const float* gc = g_Gc + (size_t)g * 128;
      char* rhi = tile_hi + (size_t)r * AROW;
      char* rlo = tile_lo + (size_t)r * AROW;
#pragma unroll
      for (int q = 0; q < 4; q++) {
        const int c = q * 32 + sub * 4;
        const float4 va = *(const float4*)(pa + c);
        const float4 vb = *(const float4*)(pb + c);
        const float4 vg = *(const float4*)(gc + c);
        float v0 = fmaxf(va.x + vb.x + vg.x, 0.f);
        float v1 = fmaxf(va.y + vb.y + vg.y, 0.f);
        float v2 = fmaxf(va.z + vb.z + vg.z, 0.f);
        float v3 = fmaxf(va.w + vb.w + vg.w, 0.f);
        const uint32_t hi01 =
            __byte_perm(__float_as_uint(v0), __float_as_uint(v1), 0x7632);
        const uint32_t hi23 =
            __byte_perm(__float_as_uint(v2), __float_as_uint(v3), 0x7632);
        const float l0 = v0 - trunc_bf16(v0);
        const float l1 = v1 - trunc_bf16(v1);
        const float l2 = v2 - trunc_bf16(v2);
        const float l3 = v3 - trunc_bf16(v3);
        const __nv_bfloat162 lp01 = __floats2bfloat162_rn(l0, l1);
        const __nv_bfloat162 lp23 = __floats2bfloat162_rn(l2, l3);
        const int qb = (q < 2) ? (q * 64 + sub * 8)
                               : (HALF_OFF + (q - 2) * 64 + sub * 8);
        *(uint2*)(rhi + qb) = make_uint2(hi01, hi23);
        *(uint2*)(rlo + qb) =
            make_uint2(*(const uint32_t*)&lp01, *(const uint32_t*)&lp23);
      }
    }
    __syncwarp();

    // ---- Phase B: 3-pass HMMA ----
    float acc[8][4];
#pragma unroll
    for (int n = 0; n < 8; n++)
#pragma unroll
      for (int q = 0; q < 4; q++) acc[n][q] = 0.f;

#pragma unroll
    for (int ks = 0; ks < 8; ks++) {
      const uint32_t kb = ks * 32 + ((ks >= 4) ? 16u : 0u);
      uint32_t ah0, ah1, ah2, ah3, al0, al1, al2, al3;
      LDSM4(ah0, ah1, ah2, ah3, ahi_ld + kb);
      LDSM4(al0, al1, al2, al3, alo_ld + kb);
#pragma unroll
      for (int np = 0; np < 4; np++) {
        const uint4 vh = Bhi4[(ks * 4 + np) * 32 + lane];
        const uint4 vl = Blo4[(ks * 4 + np) * 32 + lane];
        MMA16816(acc[2 * np], ah0, ah1, ah2, ah3, vh.x, vh.y);
        MMA16816(acc[2 * np], ah0, ah1, ah2, ah3, vl.x, vl.y);
        MMA16816(acc[2 * np], al0, al1, al2, al3, vh.x, vh.y);
        MMA16816(acc[2 * np + 1], ah0, ah1, ah2, ah3, vh.z, vh.w);
        MMA16816(acc[2 * np + 1], ah0, ah1, ah2, ah3, vl.z, vl.w);
        MMA16816(acc[2 * np + 1], al0, al1, al2, al3, vh.z, vh.w);
      }
    }

    // ---- Epilogue ----
    float s0 = 0.f, s1 = 0.f;
#pragma unroll
    for (int n = 0; n < 8; n++) {
      const int c0 = n * 8 + (lane & 3) * 2;
      const float2 b2p = *(const float2*)(b2s + c0);
      const float2 w3p = *(const float2*)(w3s + c0);
      s0 = fmaf(fmaxf(acc[n][0] + b2p.x, 0.f), w3p.x, s0);
      s0 = fmaf(fmaxf(acc[n][1] + b2p.y, 0.f), w3p.y, s0);
      s1 = fmaf(fmaxf(acc[n][2] + b2p.x, 0.f), w3p.x, s1);
      s1 = fmaf(fmaxf(acc[n][3] + b2p.y, 0.f), w3p.y, s1);
    }
    s0 += __shfl_xor_sync(0xffffffffu, s0, 1);
    s0 += __shfl_xor_sync(0xffffffffu, s0, 2);
    s1 += __shfl_xor_sync(0xffffffffu, s1, 1);
    s1 += __shfl_xor_sync(0xffffffffu, s1, 2);
    if ((lane & 3) == 0) {
      const int r0 = rbase + (lane >> 2);
      if (r0 < N) out[r0] = s0 + b3v;
      const int r1 = r0 + 8;
      if (r1 < N) out[r1] = s1 + b3v;
    }
    __syncwarp();   // protect smem tile reuse next iteration
  }
}

// ---------------------------------------------------------------------------
extern "C" void kernel_launch(void* const* d_in, const int* in_sizes, int n_in,
                              void* d_out, int out_size) {
  const int* indices = (const int*)d_in[0];
  // d_in[1] = nr (fixed 24)
  const float* x  = (const float*)d_in[2];
  const float* W1 = (const float*)d_in[3];
  const float* b1 = (const float*)d_in[4];
  const float* W2 = (const float*)d_in[5];
  const float* b2 = (const float*)d_in[6];
  const float* W3 = (const float*)d_in[7];
  const float* b3 = (const float*)d_in[8];
  float* out = (float*)d_out;

  const int N = in_sizes[0] / 23;          // 500000
  const int nodes = in_sizes[2] / 128;     // 10000
  const int G = (N - 2) / 25 + 1;          // 20000 groups
  const int ntiles = (nodes + 15) / 16;    // 625

  cudaFuncSetAttribute(precompute_P_tc,
                       cudaFuncAttributeMaxDynamicSharedMemorySize, PP_SMEM);
  cudaFuncSetAttribute(mlp_main_mma,
                       cudaFuncAttributeMaxDynamicSharedMemorySize, SMEM_BYTES);

  precompute_P_tc<<<(ntiles + 3) / 4, 128, PP_SMEM>>>(x, W1, nodes);
  group_ctx<<<G, 128>>>(indices, b1, G);
  mlp_main_mma<<<296, 256, SMEM_BYTES>>>(indices, W2, b2, W3, b3, out, N);
}

// round 10
// speedup vs baseline: 3.9610x; 1.0548x over previous
#include <cuda_runtime.h>
#include <cuda_bf16.h>
#include <cstdint>

#define NCAP 10240            // node capacity for P tables
#define GCAP 20032            // group capacity

// Scratch (device globals: no allocations allowed)
__device__ float g_P[3 * NCAP * 128];   // Pa | Pb | Pc, each [nodes][128]
__device__ float g_Gc[GCAP * 128];      // per-group ctx term (+ b1 folded)

// ---------------------------------------------------------------------------
// helpers
// ---------------------------------------------------------------------------
__device__ __forceinline__ uint32_t smem_u32(const void* p) {
  uint32_t a;
  asm("{ .reg .u64 t; cvta.to.shared.u64 t, %1; cvt.u32.u64 %0, t; }"
      : "=r"(a) : "l"(p));
  return a;
}

__device__ __forceinline__ uint32_t bpack(__nv_bfloat16 a, __nv_bfloat16 b) {
  __nv_bfloat162 t(a, b);          // .x = a (low half)
  return *reinterpret_cast<uint32_t*>(&t);
}

#define LDSM4(r0, r1, r2, r3, addr)                                          \
  asm volatile(                                                              \
      "ldmatrix.sync.aligned.m8n8.x4.shared.b16 {%0,%1,%2,%3}, [%4];"        \
      : "=r"(r0), "=r"(r1), "=r"(r2), "=r"(r3) : "r"(addr))

#define MMA16816(d, a0, a1, a2, a3, b0, b1)                                  \
  asm volatile(                                                              \
      "mma.sync.aligned.m16n8k16.row.col.f32.bf16.bf16.f32 "                 \
      "{%0,%1,%2,%3}, {%4,%5,%6,%7}, {%8,%9}, {%0,%1,%2,%3};"                \
      : "+f"((d)[0]), "+f"((d)[1]), "+f"((d)[2]), "+f"((d)[3])               \
      : "r"(a0), "r"(a1), "r"(a2), "r"(a3), "r"(b0), "r"(b1))

// truncate fp32 to bf16 (toward zero); exact residual in fp32
__device__ __forceinline__ float trunc_bf16(float v) {
  return __uint_as_float(__float_as_uint(v) & 0xffff0000u);
}

// Common A-tile geometry (shared by both MMA kernels)
#define AROW 272                       // bytes per 128-ch row (16-aligned halves)
#define HALF_OFF 144                   // byte offset of channels 64..127

// build one hi/lo B-fragment uint4 pair from two weight rows
__device__ __forceinline__ void build_bfrag(const float* w_base, int row_stride,
                                            int ng0, int ng1, int k0,
                                            uint4* hi, uint4* lo) {
  uint32_t hx[2], hy[2], lx[2], ly[2];
  const int ngs[2] = {ng0, ng1};
#pragma unroll
  for (int t = 0; t < 2; t++) {
    const float* wr = w_base + (size_t)ngs[t] * row_stride + k0;
    const float w00 = wr[0], w01 = wr[1], w10 = wr[8], w11 = wr[9];
    __nv_bfloat16 h00 = __float2bfloat16(w00);
    __nv_bfloat16 h01 = __float2bfloat16(w01);
    __nv_bfloat16 h10 = __float2bfloat16(w10);
    __nv_bfloat16 h11 = __float2bfloat16(w11);
    __nv_bfloat16 l00 = __float2bfloat16(w00 - __bfloat162float(h00));
    __nv_bfloat16 l01 = __float2bfloat16(w01 - __bfloat162float(h01));
    __nv_bfloat16 l10 = __float2bfloat16(w10 - __bfloat162float(h10));
    __nv_bfloat16 l11 = __float2bfloat16(w11 - __bfloat162float(h11));
    hx[t] = bpack(h00, h01); hy[t] = bpack(h10, h11);
    lx[t] = bpack(l00, l01); ly[t] = bpack(l10, l11);
  }
  *hi = make_uint4(hx[0], hy[0], hx[1], hy[1]);
  *lo = make_uint4(lx[0], ly[0], lx[1], ly[1]);
}

// ---------------------------------------------------------------------------
// Kernel A (tensor): P[p][n][j] = sum_k x[n][k] * W1[j][p*128+k]
// grid (ceil(ntiles/4), 3): blockIdx.y = part. Each block builds B-frags for
// its part ONCE (no serialization), 4 warps x one 16-row x tile.
// 3-pass trunc hi/lo bf16 split -> ~2^-17 relative accuracy on P.
// ---------------------------------------------------------------------------
#define PP_AHI 0
#define PP_ALO (4 * 16 * AROW)             // 17408
#define PP_BHI (2 * 4 * 16 * AROW)         // 34816
#define PP_BLO (PP_BHI + 32768)            // 67584
#define PP_SMEM (PP_BLO + 32768)           // 100352

__global__ void __launch_bounds__(128, 2) precompute_P_tc(
    const float* __restrict__ x, const float* __restrict__ W1, int nodes) {
  extern __shared__ char smem[];
  const uint32_t sbase = smem_u32(smem);
  const int tid = threadIdx.x;
  const int wid = tid >> 5;
  const int lane = tid & 31;
  const int p = blockIdx.y;

  uint4* Bhi4 = (uint4*)(smem + PP_BHI);   // [ks][np][lane], np=0..7 (16 nf)
  uint4* Blo4 = (uint4*)(smem + PP_BLO);

  const int ntiles = (nodes + 15) >> 4;
  const int wt = blockIdx.x * 4 + wid;
  const bool active = (wt < ntiles);
  const int n0 = wt << 4;

  // ---- A split: 16 x-rows -> trunc hi/lo bf16 in AROW layout ----
  const int sub = lane & 7;
  const int rgl = lane >> 3;
  char* tile_hi = smem + PP_AHI + (size_t)wid * 16 * AROW;
  char* tile_lo = smem + PP_ALO + (size_t)wid * 16 * AROW;
  if (active) {
#pragma unroll
    for (int rg = 0; rg < 4; rg++) {
      const int r = rg * 4 + rgl;
      const int gr = min(n0 + r, nodes - 1);
      const float* xr = x + (size_t)gr * 128;
      char* rhi = tile_hi + (size_t)r * AROW;
      char* rlo = tile_lo + (size_t)r * AROW;
#pragma unroll
      for (int q = 0; q < 4; q++) {
        const int c = q * 32 + sub * 4;
        const float4 v4 = *(const float4*)(xr + c);
        const uint32_t hi01 = __byte_perm(__float_as_uint(v4.x),
                                          __float_as_uint(v4.y), 0x7632);
        const uint32_t hi23 = __byte_perm(__float_as_uint(v4.z),
                                          __float_as_uint(v4.w), 0x7632);
        const float l0 = v4.x - trunc_bf16(v4.x);
        const float l1 = v4.y - trunc_bf16(v4.y);
        const float l2 = v4.z - trunc_bf16(v4.z);
        const float l3 = v4.w - trunc_bf16(v4.w);
        const __nv_bfloat162 lp01 = __floats2bfloat162_rn(l0, l1);
        const __nv_bfloat162 lp23 = __floats2bfloat162_rn(l2, l3);
        const int qb = (q < 2) ? (q * 64 + sub * 8)
                               : (HALF_OFF + (q - 2) * 64 + sub * 8);
        *(uint2*)(rhi + qb) = make_uint2(hi01, hi23);
        *(uint2*)(rlo + qb) =
            make_uint2(*(const uint32_t*)&lp01, *(const uint32_t*)&lp23);
      }
    }
  }

  // ---- build B-frags for part p: W1[ng][p*128 + k] (once per block) ----
  for (int i = tid; i < 2048; i += 128) {
    const int ln = i & 31;
    const int np = (i >> 5) & 7;
    const int ks = i >> 8;
    const int k0 = ks * 16 + (ln & 3) * 2;
    const int ng0 = (2 * np) * 8 + (ln >> 2);
    const int ng1 = (2 * np + 1) * 8 + (ln >> 2);
    build_bfrag(W1 + p * 128, 384, ng0, ng1, k0, &Bhi4[i], &Blo4[i]);
  }
  __syncthreads();

  if (!active) return;

  // ldmatrix addressing
  const uint32_t lrow = (lane < 16) ? lane : (lane - 16);
  const uint32_t lcol = (lane < 16) ? 0u : 16u;
  const uint32_t ahi_ld = sbase + PP_AHI + (wid * 16 + lrow) * AROW + lcol;
  const uint32_t alo_ld = sbase + PP_ALO + (wid * 16 + lrow) * AROW + lcol;

  float acc[16][4];
#pragma unroll
  for (int n = 0; n < 16; n++)
#pragma unroll
    for (int q = 0; q < 4; q++) acc[n][q] = 0.f;

#pragma unroll
  for (int ks = 0; ks < 8; ks++) {
    const uint32_t kb = ks * 32 + ((ks >= 4) ? 16u : 0u);
    uint32_t ah0, ah1, ah2, ah3, al0, al1, al2, al3;
    LDSM4(ah0, ah1, ah2, ah3, ahi_ld + kb);
    LDSM4(al0, al1, al2, al3, alo_ld + kb);
#pragma unroll
    for (int np = 0; np < 8; np++) {
      const uint4 vh = Bhi4[(ks * 8 + np) * 32 + lane];
      const uint4 vl = Blo4[(ks * 8 + np) * 32 + lane];
      MMA16816(acc[2 * np], ah0, ah1, ah2, ah3, vh.x, vh.y);
      MMA16816(acc[2 * np], ah0, ah1, ah2, ah3, vl.x, vl.y);
      MMA16816(acc[2 * np], al0, al1, al2, al3, vh.x, vh.y);
      MMA16816(acc[2 * np + 1], ah0, ah1, ah2, ah3, vh.z, vh.w);
      MMA16816(acc[2 * np + 1], ah0, ah1, ah2, ah3, vl.z, vl.w);
      MMA16816(acc[2 * np + 1], al0, al1, al2, al3, vh.z, vh.w);
    }
  }

  // store D -> g_P[p]; fragment mapping: rows lane>>2 and +8, cols nf*8+(lane&3)*2
  float* Pp = g_P + (size_t)p * NCAP * 128;
  const int r0 = n0 + (lane >> 2);
  const int r1 = r0 + 8;
#pragma unroll
  for (int nf = 0; nf < 16; nf++) {
    const int c0 = nf * 8 + (lane & 3) * 2;
    if (r0 < nodes)
      *(float2*)(Pp + (size_t)r0 * 128 + c0) = make_float2(acc[nf][0], acc[nf][1]);
    if (r1 < nodes)
      *(float2*)(Pp + (size_t)r1 * 128 + c0) = make_float2(acc[nf][2], acc[nf][3]);
  }
}

// ---------------------------------------------------------------------------
// Kernel B: per-group context term (+ b1 folded in)
// ---------------------------------------------------------------------------
__global__ __launch_bounds__(128) void group_ctx(
    const int* __restrict__ indices, const float* __restrict__ b1, int G) {
  const int g = blockIdx.x;
  if (g >= G) return;
  const int t = threadIdx.x;
  const int* ip = indices + (size_t)g * 25 * 23 + 3;
  const float* Pc = g_P + (size_t)2 * NCAP * 128;

  float s = 0.f;
  int cnt = 0;
#pragma unroll
  for (int kk = 0; kk < 20; kk++) {
    const int id = ip[kk];
    s += Pc[(size_t)id * 128 + t];
    cnt += (id > 0) ? 1 : 0;
  }
  const float norm = (float)(cnt > 0 ? cnt : 1);
  g_Gc[(size_t)g * 128 + t] = s / norm + b1[t];
}

// ---------------------------------------------------------------------------
// Kernel C: warp-independent HMMA MLP. Each warp owns a 16-row tile.
// ---------------------------------------------------------------------------
#define AHI_OFF 0
#define ALO_OFF (8 * 16 * AROW)        // 34816
#define BF_OFF (2 * (8 * 16 * AROW))   // 69632
#define BFRAG_U4 1024                  // (8 ks * 4 np * 32 lanes) uint4 per pass
#define MISC_OFF (BF_OFF + 2 * BFRAG_U4 * 16)  // 102400
#define SMEM_BYTES (MISC_OFF + 768)

__global__ void __launch_bounds__(256, 2) mlp_main_mma(
    const int* __restrict__ indices,
    const float* __restrict__ W2, const float* __restrict__ b2,
    const float* __restrict__ W3, const float* __restrict__ b3,
    float* __restrict__ out, int N) {
  extern __shared__ char smem[];
  const uint32_t sbase = smem_u32(smem);

  const int tid = threadIdx.x;
  const int wid = tid >> 5;
  const int lane = tid & 31;

  uint4* Bhi4 = (uint4*)(smem + BF_OFF);     // [ks][np][lane]
  uint4* Blo4 = Bhi4 + BFRAG_U4;
  float* b2s = (float*)(smem + MISC_OFF);
  float* w3s = b2s + 64;

  // ---- Build W2 bf16 hi/lo B-fragments ----
  for (int i = tid; i < BFRAG_U4; i += 256) {
    const int ln = i & 31;
    const int np = (i >> 5) & 3;
    const int ks = i >> 7;
    const int k0 = ks * 16 + (ln & 3) * 2;
    const int ng0 = (2 * np) * 8 + (ln >> 2);
    const int ng1 = (2 * np + 1) * 8 + (ln >> 2);
    build_bfrag(W2, 128, ng0, ng1, k0, &Bhi4[i], &Blo4[i]);
  }
  if (tid < 64) { b2s[tid] = b2[tid]; w3s[tid] = W3[tid]; }
  const float b3v = b3[0];
  __syncthreads();

  const float* Pa = g_P;
  const float* Pb = g_P + (size_t)NCAP * 128;

  const int sub = lane & 7;          // 16B sub-block within a 128B line
  const int rgl = lane >> 3;         // row within group of 4
  char* tile_hi = smem + AHI_OFF + (size_t)(wid * 16) * AROW;
  char* tile_lo = smem + ALO_OFF + (size_t)(wid * 16) * AROW;

  const uint32_t lrow = (lane < 16) ? lane : (lane - 16);
  const uint32_t lcol = (lane < 16) ? 0u : 16u;
  const uint32_t ahi_ld = sbase + AHI_OFF + (wid * 16 + lrow) * AROW + lcol;
  const uint32_t alo_ld = sbase + ALO_OFF + (wid * 16 + lrow) * AROW + lcol;

  const int NTW = (N + 15) >> 4;
  const int wstride = gridDim.x * 8;

  for (int wt = blockIdx.x * 8 + wid; wt < NTW; wt += wstride) {
    const int rbase = wt << 4;

    // ---- Phase A: gather + relu + truncation bf16 hi/lo split ----
#pragma unroll
    for (int rg = 0; rg < 4; rg++) {
      const int r = rg * 4 + rgl;
      const int gr = min(rbase + r, N - 1);
      const int i0 = indices[(size_t)gr * 23 + 0];
      const int i1 = indices[(size_t)gr * 23 + 1];
      const int g = gr / 25;
      const float* pa = Pa + (size_t)i0 * 128;
      const float* pb = Pb + (size_t)i1 * 128;
      const float* gc = g_Gc + (size_t)g * 128;
      char* rhi = tile_hi + (size_t)r * AROW;
      char* rlo = tile_lo + (size_t)r * AROW;
#pragma unroll
      for (int q = 0; q < 4; q++) {
        const int c = q * 32 + sub * 4;
        const float4 va = *(const float4*)(pa + c);
        const float4 vb = *(const float4*)(pb + c);
        const float4 vg = *(const float4*)(gc + c);
        float v0 = fmaxf(va.x + vb.x + vg.x, 0.f);
        float v1 = fmaxf(va.y + vb.y + vg.y, 0.f);
        float v2 = fmaxf(va.z + vb.z + vg.z, 0.f);
        float v3 = fmaxf(va.w + vb.w + vg.w, 0.f);
        const uint32_t hi01 =
            __byte_perm(__float_as_uint(v0), __float_as_uint(v1), 0x7632);
        const uint32_t hi23 =
            __byte_perm(__float_as_uint(v2), __float_as_uint(v3), 0x7632);
        const float l0 = v0 - trunc_bf16(v0);
        const float l1 = v1 - trunc_bf16(v1);
        const float l2 = v2 - trunc_bf16(v2);
        const float l3 = v3 - trunc_bf16(v3);
        const __nv_bfloat162 lp01 = __floats2bfloat162_rn(l0, l1);
        const __nv_bfloat162 lp23 = __floats2bfloat162_rn(l2, l3);
        const int qb = (q < 2) ? (q * 64 + sub * 8)
                               : (HALF_OFF + (q - 2) * 64 + sub * 8);
        *(uint2*)(rhi + qb) = make_uint2(hi01, hi23);
        *(uint2*)(rlo + qb) =
            make_uint2(*(const uint32_t*)&lp01, *(const uint32_t*)&lp23);
      }
    }
    __syncwarp();

    // ---- Phase B: 3-pass HMMA ----
    float acc[8][4];
#pragma unroll
    for (int n = 0; n < 8; n++)
#pragma unroll
      for (int q = 0; q < 4; q++) acc[n][q] = 0.f;

#pragma unroll
    for (int ks = 0; ks < 8; ks++) {
      const uint32_t kb = ks * 32 + ((ks >= 4) ? 16u : 0u);
      uint32_t ah0, ah1, ah2, ah3, al0, al1, al2, al3;
      LDSM4(ah0, ah1, ah2, ah3, ahi_ld + kb);
      LDSM4(al0, al1, al2, al3, alo_ld + kb);
#pragma unroll
      for (int np = 0; np < 4; np++) {
        const uint4 vh = Bhi4[(ks * 4 + np) * 32 + lane];
        const uint4 vl = Blo4[(ks * 4 + np) * 32 + lane];
        MMA16816(acc[2 * np], ah0, ah1, ah2, ah3, vh.x, vh.y);
        MMA16816(acc[2 * np], ah0, ah1, ah2, ah3, vl.x, vl.y);
        MMA16816(acc[2 * np], al0, al1, al2, al3, vh.x, vh.y);
        MMA16816(acc[2 * np + 1], ah0, ah1, ah2, ah3, vh.z, vh.w);
        MMA16816(acc[2 * np + 1], ah0, ah1, ah2, ah3, vl.z, vl.w);
        MMA16816(acc[2 * np + 1], al0, al1, al2, al3, vh.z, vh.w);
      }
    }

    // ---- Epilogue ----
    float s0 = 0.f, s1 = 0.f;
#pragma unroll
    for (int n = 0; n < 8; n++) {
      const int c0 = n * 8 + (lane & 3) * 2;
      const float2 b2p = *(const float2*)(b2s + c0);
      const float2 w3p = *(const float2*)(w3s + c0);
      s0 = fmaf(fmaxf(acc[n][0] + b2p.x, 0.f), w3p.x, s0);
      s0 = fmaf(fmaxf(acc[n][1] + b2p.y, 0.f), w3p.y, s0);
      s1 = fmaf(fmaxf(acc[n][2] + b2p.x, 0.f), w3p.x, s1);
      s1 = fmaf(fmaxf(acc[n][3] + b2p.y, 0.f), w3p.y, s1);
    }
    s0 += __shfl_xor_sync(0xffffffffu, s0, 1);
    s0 += __shfl_xor_sync(0xffffffffu, s0, 2);
    s1 += __shfl_xor_sync(0xffffffffu, s1, 1);
    s1 += __shfl_xor_sync(0xffffffffu, s1, 2);
    if ((lane & 3) == 0) {
      const int r0 = rbase + (lane >> 2);
      if (r0 < N) out[r0] = s0 + b3v;
      const int r1 = r0 + 8;
      if (r1 < N) out[r1] = s1 + b3v;
    }
    __syncwarp();   // protect smem tile reuse next iteration
  }
}

// ---------------------------------------------------------------------------
extern "C" void kernel_launch(void* const* d_in, const int* in_sizes, int n_in,
                              void* d_out, int out_size) {
  const int* indices = (const int*)d_in[0];
  // d_in[1] = nr (fixed 24)
  const float* x  = (const float*)d_in[2];
  const float* W1 = (const float*)d_in[3];
  const float* b1 = (const float*)d_in[4];
  const float* W2 = (const float*)d_in[5];
  const float* b2 = (const float*)d_in[6];
  const float* W3 = (const float*)d_in[7];
  const float* b3 = (const float*)d_in[8];
  float* out = (float*)d_out;

  const int N = in_sizes[0] / 23;          // 500000
  const int nodes = in_sizes[2] / 128;     // 10000
  const int G = (N - 2) / 25 + 1;          // 20000 groups
  const int ntiles = (nodes + 15) / 16;    // 625

  cudaFuncSetAttribute(precompute_P_tc,
                       cudaFuncAttributeMaxDynamicSharedMemorySize, PP_SMEM);
  cudaFuncSetAttribute(mlp_main_mma,
                       cudaFuncAttributeMaxDynamicSharedMemorySize, SMEM_BYTES);

  dim3 gridP((ntiles + 3) / 4, 3);
  precompute_P_tc<<<gridP, 128, PP_SMEM>>>(x, W1, nodes);
  group_ctx<<<G, 128>>>(indices, b1, G);
  mlp_main_mma<<<296, 256, SMEM_BYTES>>>(indices, W2, b2, W3, b3, out, N);
}

// round 11
// speedup vs baseline: 4.0350x; 1.0187x over previous
#include <cuda_runtime.h>
#include <cuda_bf16.h>
#include <cstdint>

#define NCAP 10240            // node capacity for P tables
#define GCAP 20032            // group capacity

// Scratch (device globals: no allocations allowed)
__device__ float g_P[3 * NCAP * 128];   // Pa | Pb | Pc, each [nodes][128]
__device__ float g_Gc[GCAP * 128];      // per-group ctx term (+ b1 folded)

// Prebuilt weight fragments: tables 0..2 = W1 parts (2048 u4), 3 = W2 (1024 u4)
__device__ uint4 g_Wf_hi[4][2048];
__device__ uint4 g_Wf_lo[4][2048];

// ---------------------------------------------------------------------------
// helpers
// ---------------------------------------------------------------------------
__device__ __forceinline__ uint32_t smem_u32(const void* p) {
  uint32_t a;
  asm("{ .reg .u64 t; cvta.to.shared.u64 t, %1; cvt.u32.u64 %0, t; }"
      : "=r"(a) : "l"(p));
  return a;
}

__device__ __forceinline__ uint32_t bpack(__nv_bfloat16 a, __nv_bfloat16 b) {
  __nv_bfloat162 t(a, b);          // .x = a (low half)
  return *reinterpret_cast<uint32_t*>(&t);
}

#define LDSM4(r0, r1, r2, r3, addr)                                          \
  asm volatile(                                                              \
      "ldmatrix.sync.aligned.m8n8.x4.shared.b16 {%0,%1,%2,%3}, [%4];"        \
      : "=r"(r0), "=r"(r1), "=r"(r2), "=r"(r3) : "r"(addr))

#define MMA16816(d, a0, a1, a2, a3, b0, b1)                                  \
  asm volatile(                                                              \
      "mma.sync.aligned.m16n8k16.row.col.f32.bf16.bf16.f32 "                 \
      "{%0,%1,%2,%3}, {%4,%5,%6,%7}, {%8,%9}, {%0,%1,%2,%3};"                \
      : "+f"((d)[0]), "+f"((d)[1]), "+f"((d)[2]), "+f"((d)[3])               \
      : "r"(a0), "r"(a1), "r"(a2), "r"(a3), "r"(b0), "r"(b1))

// truncate fp32 to bf16 (toward zero); exact residual in fp32
__device__ __forceinline__ float trunc_bf16(float v) {
  return __uint_as_float(__float_as_uint(v) & 0xffff0000u);
}

// Common A-tile geometry (shared by both MMA kernels)
#define AROW 272                       // bytes per 128-ch row (16-aligned halves)
#define HALF_OFF 144                   // byte offset of channels 64..127

// build one hi/lo B-fragment uint4 pair from two weight rows
__device__ __forceinline__ void build_bfrag(const float* w_base, int row_stride,
                                            int ng0, int ng1, int k0,
                                            uint4* hi, uint4* lo) {
  uint32_t hx[2], hy[2], lx[2], ly[2];
  const int ngs[2] = {ng0, ng1};
#pragma unroll
  for (int t = 0; t < 2; t++) {
    const float* wr = w_base + (size_t)ngs[t] * row_stride + k0;
    const float w00 = wr[0], w01 = wr[1], w10 = wr[8], w11 = wr[9];
    __nv_bfloat16 h00 = __float2bfloat16(w00);
    __nv_bfloat16 h01 = __float2bfloat16(w01);
    __nv_bfloat16 h10 = __float2bfloat16(w10);
    __nv_bfloat16 h11 = __float2bfloat16(w11);
    __nv_bfloat16 l00 = __float2bfloat16(w00 - __bfloat162float(h00));
    __nv_bfloat16 l01 = __float2bfloat16(w01 - __bfloat162float(h01));
    __nv_bfloat16 l10 = __float2bfloat16(w10 - __bfloat162float(h10));
    __nv_bfloat16 l11 = __float2bfloat16(w11 - __bfloat162float(h11));
    hx[t] = bpack(h00, h01); hy[t] = bpack(h10, h11);
    lx[t] = bpack(l00, l01); ly[t] = bpack(l10, l11);
  }
  *hi = make_uint4(hx[0], hy[0], hx[1], hy[1]);
  *lo = make_uint4(lx[0], ly[0], lx[1], ly[1]);
}

// ---------------------------------------------------------------------------
// Kernel 0: build all weight fragments ONCE into device globals.
// grid (8, 4): blockIdx.y = table (0..2 W1 part, 3 = W2), 256 thr.
// ---------------------------------------------------------------------------
__global__ __launch_bounds__(256) void build_wfrags(
    const float* __restrict__ W1, const float* __restrict__ W2) {
  const int tab = blockIdx.y;
  const int i = blockIdx.x * 256 + threadIdx.x;
  const int count = (tab == 3) ? 1024 : 2048;
  if (i >= count) return;

  const int ln = i & 31;
  const int npw = (tab == 3) ? ((i >> 5) & 3) : ((i >> 5) & 7);
  const int ks = (tab == 3) ? (i >> 7) : (i >> 8);
  const int k0 = ks * 16 + (ln & 3) * 2;
  const int ng0 = (2 * npw) * 8 + (ln >> 2);
  const int ng1 = (2 * npw + 1) * 8 + (ln >> 2);

  uint4 hi, lo;
  if (tab == 3) build_bfrag(W2, 128, ng0, ng1, k0, &hi, &lo);
  else          build_bfrag(W1 + tab * 128, 384, ng0, ng1, k0, &hi, &lo);
  g_Wf_hi[tab][i] = hi;
  g_Wf_lo[tab][i] = lo;
}

// ---------------------------------------------------------------------------
// Kernel A (tensor): P[p][n][j] = sum_k x[n][k] * W1[j][p*128+k]
// grid (ceil(ntiles/4), 3): blockIdx.y = part. Fragments COPIED coalesced
// from g_Wf (no scattered build). 4 warps x one 16-row x tile.
// ---------------------------------------------------------------------------
#define PP_AHI 0
#define PP_ALO (4 * 16 * AROW)             // 17408
#define PP_BHI (2 * 4 * 16 * AROW)         // 34816
#define PP_BLO (PP_BHI + 32768)            // 67584
#define PP_SMEM (PP_BLO + 32768)           // 100352

__global__ void __launch_bounds__(128, 2) precompute_P_tc(
    const float* __restrict__ x, int nodes) {
  extern __shared__ char smem[];
  const uint32_t sbase = smem_u32(smem);
  const int tid = threadIdx.x;
  const int wid = tid >> 5;
  const int lane = tid & 31;
  const int p = blockIdx.y;

  uint4* Bhi4 = (uint4*)(smem + PP_BHI);   // [ks][np][lane], np=0..7 (16 nf)
  uint4* Blo4 = (uint4*)(smem + PP_BLO);

  const int ntiles = (nodes + 15) >> 4;
  const int wt = blockIdx.x * 4 + wid;
  const bool active = (wt < ntiles);
  const int n0 = wt << 4;

  // ---- coalesced fragment copy from global (prebuilt) ----
  {
    const uint4* sh = g_Wf_hi[p];
    const uint4* sl = g_Wf_lo[p];
    for (int i = tid; i < 2048; i += 128) {
      Bhi4[i] = sh[i];
      Blo4[i] = sl[i];
    }
  }

  // ---- A split: 16 x-rows -> trunc hi/lo bf16 in AROW layout ----
  const int sub = lane & 7;
  const int rgl = lane >> 3;
  char* tile_hi = smem + PP_AHI + (size_t)wid * 16 * AROW;
  char* tile_lo = smem + PP_ALO + (size_t)wid * 16 * AROW;
  if (active) {
#pragma unroll
    for (int rg = 0; rg < 4; rg++) {
      const int r = rg * 4 + rgl;
      const int gr = min(n0 + r, nodes - 1);
      const float* xr = x + (size_t)gr * 128;
      char* rhi = tile_hi + (size_t)r * AROW;
      char* rlo = tile_lo + (size_t)r * AROW;
#pragma unroll
      for (int q = 0; q < 4; q++) {
        const int c = q * 32 + sub * 4;
        const float4 v4 = *(const float4*)(xr + c);
        const uint32_t hi01 = __byte_perm(__float_as_uint(v4.x),
                                          __float_as_uint(v4.y), 0x7632);
        const uint32_t hi23 = __byte_perm(__float_as_uint(v4.z),
                                          __float_as_uint(v4.w), 0x7632);
        const float l0 = v4.x - trunc_bf16(v4.x);
        const float l1 = v4.y - trunc_bf16(v4.y);
        const float l2 = v4.z - trunc_bf16(v4.z);
        const float l3 = v4.w - trunc_bf16(v4.w);
        const __nv_bfloat162 lp01 = __floats2bfloat162_rn(l0, l1);
        const __nv_bfloat162 lp23 = __floats2bfloat162_rn(l2, l3);
        const int qb = (q < 2) ? (q * 64 + sub * 8)
                               : (HALF_OFF + (q - 2) * 64 + sub * 8);
        *(uint2*)(rhi + qb) = make_uint2(hi01, hi23);
        *(uint2*)(rlo + qb) =
            make_uint2(*(const uint32_t*)&lp01, *(const uint32_t*)&lp23);
      }
    }
  }
  __syncthreads();

  if (!active) return;

  // ldmatrix addressing
  const uint32_t lrow = (lane < 16) ? lane : (lane - 16);
  const uint32_t lcol = (lane < 16) ? 0u : 16u;
  const uint32_t ahi_ld = sbase + PP_AHI + (wid * 16 + lrow) * AROW + lcol;
  const uint32_t alo_ld = sbase + PP_ALO + (wid * 16 + lrow) * AROW + lcol;

  float acc[16][4];
#pragma unroll
  for (int n = 0; n < 16; n++)
#pragma unroll
    for (int q = 0; q < 4; q++) acc[n][q] = 0.f;

#pragma unroll
  for (int ks = 0; ks < 8; ks++) {
    const uint32_t kb = ks * 32 + ((ks >= 4) ? 16u : 0u);
    uint32_t ah0, ah1, ah2, ah3, al0, al1, al2, al3;
    LDSM4(ah0, ah1, ah2, ah3, ahi_ld + kb);
    LDSM4(al0, al1, al2, al3, alo_ld + kb);
#pragma unroll
    for (int np = 0; np < 8; np++) {
      const uint4 vh = Bhi4[(ks * 8 + np) * 32 + lane];
      const uint4 vl = Blo4[(ks * 8 + np) * 32 + lane];
      MMA16816(acc[2 * np], ah0, ah1, ah2, ah3, vh.x, vh.y);
      MMA16816(acc[2 * np], ah0, ah1, ah2, ah3, vl.x, vl.y);
      MMA16816(acc[2 * np], al0, al1, al2, al3, vh.x, vh.y);
      MMA16816(acc[2 * np + 1], ah0, ah1, ah2, ah3, vh.z, vh.w);
      MMA16816(acc[2 * np + 1], ah0, ah1, ah2, ah3, vl.z, vl.w);
      MMA16816(acc[2 * np + 1], al0, al1, al2, al3, vh.z, vh.w);
    }
  }

  // store D -> g_P[p]; fragment mapping: rows lane>>2 and +8, cols nf*8+(lane&3)*2
  float* Pp = g_P + (size_t)p * NCAP * 128;
  const int r0 = n0 + (lane >> 2);
  const int r1 = r0 + 8;
#pragma unroll
  for (int nf = 0; nf < 16; nf++) {
    const int c0 = nf * 8 + (lane & 3) * 2;
    if (r0 < nodes)
      *(float2*)(Pp + (size_t)r0 * 128 + c0) = make_float2(acc[nf][0], acc[nf][1]);
    if (r1 < nodes)
      *(float2*)(Pp + (size_t)r1 * 128 + c0) = make_float2(acc[nf][2], acc[nf][3]);
  }
}

// ---------------------------------------------------------------------------
// Kernel B: per-group context term (+ b1 folded in)
// ---------------------------------------------------------------------------
__global__ __launch_bounds__(128) void group_ctx(
    const int* __restrict__ indices, const float* __restrict__ b1, int G) {
  const int g = blockIdx.x;
  if (g >= G) return;
  const int t = threadIdx.x;
  const int* ip = indices + (size_t)g * 25 * 23 + 3;
  const float* Pc = g_P + (size_t)2 * NCAP * 128;

  float s = 0.f;
  int cnt = 0;
#pragma unroll
  for (int kk = 0; kk < 20; kk++) {
    const int id = ip[kk];
    s += Pc[(size_t)id * 128 + t];
    cnt += (id > 0) ? 1 : 0;
  }
  const float norm = (float)(cnt > 0 ? cnt : 1);
  g_Gc[(size_t)g * 128 + t] = s / norm + b1[t];
}

// ---------------------------------------------------------------------------
// Kernel C: warp-independent HMMA MLP. Each warp owns a 16-row tile.
// ---------------------------------------------------------------------------
#define AHI_OFF 0
#define ALO_OFF (8 * 16 * AROW)        // 34816
#define BF_OFF (2 * (8 * 16 * AROW))   // 69632
#define BFRAG_U4 1024                  // (8 ks * 4 np * 32 lanes) uint4 per pass
#define MISC_OFF (BF_OFF + 2 * BFRAG_U4 * 16)  // 102400
#define SMEM_BYTES (MISC_OFF + 768)

__global__ void __launch_bounds__(256, 2) mlp_main_mma(
    const int* __restrict__ indices,
    const float* __restrict__ b2, const float* __restrict__ W3,
    const float* __restrict__ b3,
    float* __restrict__ out, int N) {
  extern __shared__ char smem[];
  const uint32_t sbase = smem_u32(smem);

  const int tid = threadIdx.x;
  const int wid = tid >> 5;
  const int lane = tid & 31;

  uint4* Bhi4 = (uint4*)(smem + BF_OFF);     // [ks][np][lane]
  uint4* Blo4 = Bhi4 + BFRAG_U4;
  float* b2s = (float*)(smem + MISC_OFF);
  float* w3s = b2s + 64;

  // ---- coalesced W2 fragment copy (prebuilt, table 3) ----
  {
    const uint4* sh = g_Wf_hi[3];
    const uint4* sl = g_Wf_lo[3];
    for (int i = tid; i < BFRAG_U4; i += 256) {
      Bhi4[i] = sh[i];
      Blo4[i] = sl[i];
    }
  }
  if (tid < 64) { b2s[tid] = b2[tid]; w3s[tid] = W3[tid]; }
  const float b3v = b3[0];
  __syncthreads();

  const float* Pa = g_P;
  const float* Pb = g_P + (size_t)NCAP * 128;

  const int sub = lane & 7;          // 16B sub-block within a 128B line
  const int rgl = lane >> 3;         // row within group of 4
  char* tile_hi = smem + AHI_OFF + (size_t)(wid * 16) * AROW;
  char* tile_lo = smem + ALO_OFF + (size_t)(wid * 16) * AROW;

  const uint32_t lrow = (lane < 16) ? lane : (lane - 16);
  const uint32_t lcol = (lane < 16) ? 0u : 16u;
  const uint32_t ahi_ld = sbase + AHI_OFF + (wid * 16 + lrow) * AROW + lcol;
  const uint32_t alo_ld = sbase + ALO_OFF + (wid * 16 + lrow) * AROW + lcol;

  const int NTW = (N + 15) >> 4;
  const int wstride = gridDim.x * 8;

  for (int wt = blockIdx.x * 8 + wid; wt < NTW; wt += wstride) {
    const int rbase = wt << 4;

    // ---- Phase A: gather + relu + truncation bf16 hi/lo split ----
#pragma unroll
    for (int rg = 0; rg < 4; rg++) {
      const int r = rg * 4 + rgl;
      const int gr = min(rbase + r, N - 1);
      const int i0 = indices[(size_t)gr * 23 + 0];
      const int i1 = indices[(size_t)gr * 23 + 1];
      const int g = gr / 25;
      const float* pa = Pa + (size_t)i0 * 128;
      const float* pb = Pb + (size_t)i1 * 128;
      const float* gc = g_Gc + (size_t)g * 128;
      char* rhi = tile_hi + (size_t)r * AROW;
      char* rlo = tile_lo + (size_t)r * AROW;
#pragma unroll
      for (int q = 0; q < 4; q++) {
        const int c = q * 32 + sub * 4;
        const float4 va = *(const float4*)(pa + c);
        const float4 vb = *(const float4*)(pb + c);
        const float4 vg = *(const float4*)(gc + c);
        float v0 = fmaxf(va.x + vb.x + vg.x, 0.f);
        float v1 = fmaxf(va.y + vb.y + vg.y, 0.f);
        float v2 = fmaxf(va.z + vb.z + vg.z, 0.f);
        float v3 = fmaxf(va.w + vb.w + vg.w, 0.f);
        const uint32_t hi01 =
            __byte_perm(__float_as_uint(v0), __float_as_uint(v1), 0x7632);
        const uint32_t hi23 =
            __byte_perm(__float_as_uint(v2), __float_as_uint(v3), 0x7632);
        const float l0 = v0 - trunc_bf16(v0);
        const float l1 = v1 - trunc_bf16(v1);
        const float l2 = v2 - trunc_bf16(v2);
        const float l3 = v3 - trunc_bf16(v3);
        const __nv_bfloat162 lp01 = __floats2bfloat162_rn(l0, l1);
        const __nv_bfloat162 lp23 = __floats2bfloat162_rn(l2, l3);
        const int qb = (q < 2) ? (q * 64 + sub * 8)
                               : (HALF_OFF + (q - 2) * 64 + sub * 8);
        *(uint2*)(rhi + qb) = make_uint2(hi01, hi23);
        *(uint2*)(rlo + qb) =
            make_uint2(*(const uint32_t*)&lp01, *(const uint32_t*)&lp23);
      }
    }
    __syncwarp();

    // ---- Phase B: 3-pass HMMA ----
    float acc[8][4];
#pragma unroll
    for (int n = 0; n < 8; n++)
#pragma unroll
      for (int q = 0; q < 4; q++) acc[n][q] = 0.f;

#pragma unroll
    for (int ks = 0; ks < 8; ks++) {
      const uint32_t kb = ks * 32 + ((ks >= 4) ? 16u : 0u);
      uint32_t ah0, ah1, ah2, ah3, al0, al1, al2, al3;
      LDSM4(ah0, ah1, ah2, ah3, ahi_ld + kb);
      LDSM4(al0, al1, al2, al3, alo_ld + kb);
#pragma unroll
      for (int np = 0; np < 4; np++) {
        const uint4 vh = Bhi4[(ks * 4 + np) * 32 + lane];
        const uint4 vl = Blo4[(ks * 4 + np) * 32 + lane];
        MMA16816(acc[2 * np], ah0, ah1, ah2, ah3, vh.x, vh.y);
        MMA16816(acc[2 * np], ah0, ah1, ah2, ah3, vl.x, vl.y);
        MMA16816(acc[2 * np], al0, al1, al2, al3, vh.x, vh.y);
        MMA16816(acc[2 * np + 1], ah0, ah1, ah2, ah3, vh.z, vh.w);
        MMA16816(acc[2 * np + 1], ah0, ah1, ah2, ah3, vl.z, vl.w);
        MMA16816(acc[2 * np + 1], al0, al1, al2, al3, vh.z, vh.w);
      }
    }

    // ---- Epilogue ----
    float s0 = 0.f, s1 = 0.f;
#pragma unroll
    for (int n = 0; n < 8; n++) {
      const int c0 = n * 8 + (lane & 3) * 2;
      const float2 b2p = *(const float2*)(b2s + c0);
      const float2 w3p = *(const float2*)(w3s + c0);
      s0 = fmaf(fmaxf(acc[n][0] + b2p.x, 0.f), w3p.x, s0);
      s0 = fmaf(fmaxf(acc[n][1] + b2p.y, 0.f), w3p.y, s0);
      s1 = fmaf(fmaxf(acc[n][2] + b2p.x, 0.f), w3p.x, s1);
      s1 = fmaf(fmaxf(acc[n][3] + b2p.y, 0.f), w3p.y, s1);
    }
    s0 += __shfl_xor_sync(0xffffffffu, s0, 1);
    s0 += __shfl_xor_sync(0xffffffffu, s0, 2);
    s1 += __shfl_xor_sync(0xffffffffu, s1, 1);
    s1 += __shfl_xor_sync(0xffffffffu, s1, 2);
    if ((lane & 3) == 0) {
      const int r0 = rbase + (lane >> 2);
      if (r0 < N) out[r0] = s0 + b3v;
      const int r1 = r0 + 8;
      if (r1 < N) out[r1] = s1 + b3v;
    }
    __syncwarp();   // protect smem tile reuse next iteration
  }
}

// ---------------------------------------------------------------------------
extern "C" void kernel_launch(void* const* d_in, const int* in_sizes, int n_in,
                              void* d_out, int out_size) {
  const int* indices = (const int*)d_in[0];
  // d_in[1] = nr (fixed 24)
  const float* x  = (const float*)d_in[2];
  const float* W1 = (const float*)d_in[3];
  const float* b1 = (const float*)d_in[4];
  const float* W2 = (const float*)d_in[5];
  const float* b2 = (const float*)d_in[6];
  const float* W3 = (const float*)d_in[7];
  const float* b3 = (const float*)d_in[8];
  float* out = (float*)d_out;

  const int N = in_sizes[0] / 23;          // 500000
  const int nodes = in_sizes[2] / 128;     // 10000
  const int G = (N - 2) / 25 + 1;          // 20000 groups
  const int ntiles = (nodes + 15) / 16;    // 625

  cudaFuncSetAttribute(precompute_P_tc,
                       cudaFuncAttributeMaxDynamicSharedMemorySize, PP_SMEM);
  cudaFuncSetAttribute(mlp_main_mma,
                       cudaFuncAttributeMaxDynamicSharedMemorySize, SMEM_BYTES);

  dim3 gridW(8, 4);
  build_wfrags<<<gridW, 256>>>(W1, W2);
  dim3 gridP((ntiles + 3) / 4, 3);
  precompute_P_tc<<<gridP, 128, PP_SMEM>>>(x, nodes);
  group_ctx<<<G, 128>>>(indices, b1, G);
  mlp_main_mma<<<296, 256, SMEM_BYTES>>>(indices, b2, W3, b3, out, N);
}